// round 2
// baseline (speedup 1.0000x reference)
#include <cuda_runtime.h>
#include <cstdint>
#include <cstddef>

#define BB   64
#define TT   31
#define SS   32
#define VV   34004
#define EE   300
#define HH   512
#define MD   1024
#define BH   (BB*HH)          // 32768
#define Z4H  2048             // 4*H

typedef unsigned long long ull;

// ----------------------------- device scratch --------------------------------
__device__ __align__(16) float g_keys[BB*SS*HH];        // 4 MB
__device__ __align__(16) float g_x[BB*TT*EE];           // gathered embeddings
__device__ __align__(16) float g_hbuf[BH];
__device__ __align__(16) float g_cbuf[BH];
__device__ __align__(16) float g_ctxbuf[BB*MD];
__device__ __align__(16) float g_zp[3*BB*Z4H];          // 3 split-K partials of z
__device__ __align__(16) float g_pa[4*TT*BH];           // attn2 split-K partials per step
__device__ __align__(16) float g_attn2all[BB*TT*HH];    // reduced attn2, row = b*T+t

// ----------------------------- helpers ---------------------------------------
__device__ __forceinline__ ull pack2(float x, float y) {
    ull r; asm("mov.b64 %0, {%1,%2};" : "=l"(r) : "f"(x), "f"(y)); return r;
}
__device__ __forceinline__ ull fma2(ull a, ull b, ull c) {
    ull d; asm("fma.rn.f32x2 %0, %1, %2, %3;" : "=l"(d) : "l"(a), "l"(b), "l"(c)); return d;
}
__device__ __forceinline__ float2 unpack2(ull a) {
    float2 f; asm("mov.b64 {%0,%1}, %2;" : "=f"(f.x), "=f"(f.y) : "l"(a)); return f;
}

// ----------------------------- init: tokens + embedding gather ---------------
__global__ void k_init(const void* __restrict__ dec,
                       const float* __restrict__ h0,
                       const float* __restrict__ c0,
                       const float* __restrict__ emb) {
    int idx = blockIdx.x * blockDim.x + threadIdx.x;
    // Probe int64 vs int32 token storage (uniform decision, all threads agree).
    const long long* p64 = (const long long*)dec;
    bool is64 = true;
#pragma unroll
    for (int i = 0; i < 4; i++) {
        long long v = p64[i];
        if (v < 0 || v >= VV) is64 = false;
    }
    if (idx < BB*TT*EE) {
        int i = idx / EE;           // i = b*T + t
        int e = idx - i*EE;
        long long tok = is64 ? p64[i] : (long long)((const int*)dec)[i];
        g_x[idx] = emb[(size_t)tok * EE + e];
    }
    if (idx < BH) {
        g_hbuf[idx] = h0[idx];
        g_cbuf[idx] = c0[idx];
    }
}

// ----------------------------- keys GEMM: [2048x1024]@[1024x512] -------------
__global__ void __launch_bounds__(256) k_keys(const float* __restrict__ memory,
                                              const float* __restrict__ Wm) {
    __shared__ float As[16][65];
    __shared__ float Bs[16][64];
    int bm = blockIdx.y * 64;
    int bn = blockIdx.x * 64;
    int tid = threadIdx.x;
    int tm = (tid >> 4) * 4;
    int tn = (tid & 15) * 4;
    ull acc[4][2];
#pragma unroll
    for (int i = 0; i < 4; i++) { acc[i][0] = 0ull; acc[i][1] = 0ull; }

    for (int kb = 0; kb < MD; kb += 16) {
        int m  = tid >> 2, ks = (tid & 3) * 4;
        float4 a4 = *(const float4*)(memory + (size_t)(bm + m) * MD + kb + ks);
        As[ks+0][m] = a4.x; As[ks+1][m] = a4.y; As[ks+2][m] = a4.z; As[ks+3][m] = a4.w;
        int kl = tid >> 4, c = (tid & 15) * 4;
        *(float4*)&Bs[kl][c] = *(const float4*)(Wm + (size_t)(kb + kl) * HH + bn + c);
        __syncthreads();
#pragma unroll
        for (int k = 0; k < 16; k++) {
            float a0 = As[k][tm+0], a1 = As[k][tm+1], a2v = As[k][tm+2], a3 = As[k][tm+3];
            float4 bq = *(const float4*)&Bs[k][tn];
            ull bp0 = pack2(bq.x, bq.y), bp1 = pack2(bq.z, bq.w);
            ull p;
            p = pack2(a0,a0);  acc[0][0]=fma2(p,bp0,acc[0][0]); acc[0][1]=fma2(p,bp1,acc[0][1]);
            p = pack2(a1,a1);  acc[1][0]=fma2(p,bp0,acc[1][0]); acc[1][1]=fma2(p,bp1,acc[1][1]);
            p = pack2(a2v,a2v);acc[2][0]=fma2(p,bp0,acc[2][0]); acc[2][1]=fma2(p,bp1,acc[2][1]);
            p = pack2(a3,a3);  acc[3][0]=fma2(p,bp0,acc[3][0]); acc[3][1]=fma2(p,bp1,acc[3][1]);
        }
        __syncthreads();
    }
#pragma unroll
    for (int i = 0; i < 4; i++) {
        float2 v0 = unpack2(acc[i][0]), v1 = unpack2(acc[i][1]);
        float4 o; o.x = v0.x; o.y = v0.y; o.z = v1.x; o.w = v1.y;
        *(float4*)(g_keys + (size_t)(bm + tm + i) * HH + bn + tn) = o;
    }
}

// ----------------------------- LSTM z partials (3-way split-K) ---------------
// split 0: x(300)@Wk[0:300]      split 1: attn_prev(512)@Wk[300:812]
// split 2: h(512)@Wr
__global__ void __launch_bounds__(256) k_lstm_z(const float* __restrict__ Wk,
                                                const float* __restrict__ Wr,
                                                int t) {
    int split = blockIdx.y;
    int bn = blockIdx.x * 32;
    int K = (split == 0) ? EE : HH;
    __shared__ float As[16][64];
    __shared__ float Bs[16][32];
    int tid = threadIdx.x;
    int tm = (tid >> 3) * 2;
    int tn = (tid & 7) * 4;
    ull acc[2][2] = {{0ull,0ull},{0ull,0ull}};

    for (int kb = 0; kb < K; kb += 16) {
#pragma unroll
        for (int u = 0; u < 4; u++) {
            int e = tid + 256*u;
            int m = e & 63, kl = e >> 6;
            int k = kb + kl;
            float av = 0.f;
            if (k < K) {
                if (split == 0)      av = g_x[((size_t)m*TT + t)*EE + k];
                else if (split == 2) av = g_hbuf[m*HH + k];
                else if (t > 0) {
                    size_t base = (size_t)((t-1)*4)*BH + m*HH + k;
                    av = g_pa[base] + g_pa[base+BH] + g_pa[base+2*(size_t)BH] + g_pa[base+3*(size_t)BH];
                }
            }
            As[kl][m] = av;
        }
#pragma unroll
        for (int u = 0; u < 2; u++) {
            int e = tid + 256*u;
            int n = e & 31, kl = e >> 5;
            int k = kb + kl;
            float bv = 0.f;
            if (k < K) {
                if (split == 2)      bv = Wr[(size_t)k*Z4H + bn + n];
                else if (split == 1) bv = Wk[(size_t)(300 + k)*Z4H + bn + n];
                else                 bv = Wk[(size_t)k*Z4H + bn + n];
            }
            Bs[kl][n] = bv;
        }
        __syncthreads();
#pragma unroll
        for (int k = 0; k < 16; k++) {
            float a0 = As[k][tm], a1 = As[k][tm+1];
            float4 b4 = *(const float4*)&Bs[k][tn];
            ull bp0 = pack2(b4.x, b4.y), bp1 = pack2(b4.z, b4.w);
            ull a20 = pack2(a0, a0), a21 = pack2(a1, a1);
            acc[0][0] = fma2(a20, bp0, acc[0][0]);
            acc[0][1] = fma2(a20, bp1, acc[0][1]);
            acc[1][0] = fma2(a21, bp0, acc[1][0]);
            acc[1][1] = fma2(a21, bp1, acc[1][1]);
        }
        __syncthreads();
    }
    float* zp = g_zp + (size_t)split * BB * Z4H;
#pragma unroll
    for (int i = 0; i < 2; i++) {
        float2 v0 = unpack2(acc[i][0]), v1 = unpack2(acc[i][1]);
        float4 o; o.x = v0.x; o.y = v0.y; o.z = v1.x; o.w = v1.y;
        *(float4*)(zp + (size_t)(tm + i) * Z4H + bn + tn) = o;
    }
}

// ------------- fused gates + Bahdanau (q, score, softmax, ctx) per batch -----
__global__ void __launch_bounds__(256) k_attn(const float* __restrict__ memory,
                                              const float* __restrict__ Wq,
                                              const float* __restrict__ vvec,
                                              const float* __restrict__ bias) {
    int b = blockIdx.x;
    int tid = threadIdx.x;
    __shared__ float h2s[HH];
    __shared__ float qs[HH];
    __shared__ float vs[HH];
    __shared__ float sc[SS];

    const size_t BZ = (size_t)BB * Z4H;
    // gates
#pragma unroll
    for (int u = 0; u < 2; u++) {
        int hh = tid + 256*u;
        size_t base = (size_t)b * Z4H + hh;
        float zi = g_zp[base]            + g_zp[BZ+base]            + g_zp[2*BZ+base]            + bias[hh];
        float zf = g_zp[base+512]        + g_zp[BZ+base+512]        + g_zp[2*BZ+base+512]        + bias[hh+512];
        float zg = g_zp[base+1024]       + g_zp[BZ+base+1024]       + g_zp[2*BZ+base+1024]       + bias[hh+1024];
        float zo = g_zp[base+1536]       + g_zp[BZ+base+1536]       + g_zp[2*BZ+base+1536]       + bias[hh+1536];
        float ii = 1.f / (1.f + expf(-zi));
        float ff = 1.f / (1.f + expf(-zf));
        float oo = 1.f / (1.f + expf(-zo));
        float c2 = ff * g_cbuf[b*HH + hh] + ii * tanhf(zg);
        float h2 = oo * tanhf(c2);
        g_cbuf[b*HH + hh] = c2;
        g_hbuf[b*HH + hh] = h2;
        h2s[hh] = h2;
        vs[hh]  = vvec[hh];
    }
    __syncthreads();
    // q = h2 @ Wq
#pragma unroll
    for (int u = 0; u < 2; u++) {
        int hh = tid + 256*u;
        float s0=0.f, s1=0.f, s2=0.f, s3=0.f;
        for (int k = 0; k < HH; k += 4) {
            s0 += h2s[k+0] * Wq[(size_t)(k+0)*HH + hh];
            s1 += h2s[k+1] * Wq[(size_t)(k+1)*HH + hh];
            s2 += h2s[k+2] * Wq[(size_t)(k+2)*HH + hh];
            s3 += h2s[k+3] * Wq[(size_t)(k+3)*HH + hh];
        }
        qs[hh] = (s0+s1) + (s2+s3);
    }
    __syncthreads();
    // scores
    int w = tid >> 5, lane = tid & 31;
#pragma unroll
    for (int si = 0; si < 4; si++) {
        int s = w*4 + si;
        const float* kp = g_keys + ((size_t)(b*SS + s)) * HH;
        float acc = 0.f;
        for (int h = lane; h < HH; h += 32)
            acc += tanhf(kp[h] + qs[h]) * vs[h];
#pragma unroll
        for (int off = 16; off; off >>= 1)
            acc += __shfl_down_sync(0xffffffffu, acc, off);
        if (lane == 0) sc[s] = acc;
    }
    __syncthreads();
    // softmax over 32 (warp 0)
    if (tid < 32) {
        float x = sc[tid];
        float mx = x;
#pragma unroll
        for (int off = 16; off; off >>= 1) mx = fmaxf(mx, __shfl_xor_sync(0xffffffffu, mx, off));
        float e = expf(x - mx);
        float sm = e;
#pragma unroll
        for (int off = 16; off; off >>= 1) sm += __shfl_xor_sync(0xffffffffu, sm, off);
        sc[tid] = e / sm;
    }
    __syncthreads();
    // ctx = al @ memory[b]
    const float* mp = memory + (size_t)b * SS * MD;
#pragma unroll
    for (int u = 0; u < 4; u++) {
        int m = tid + 256*u;
        float acc = 0.f;
#pragma unroll
        for (int s = 0; s < SS; s++) acc += sc[s] * mp[(size_t)s*MD + m];
        g_ctxbuf[b*MD + m] = acc;
    }
}

// ------------- attn2 partials: concat(h2,ctx)[64x1536] @ Wa[1536x512], splitK4
__global__ void __launch_bounds__(256) k_attn2(const float* __restrict__ Wa, int t) {
    int kc = blockIdx.y;                // K chunk of 384
    int bn = blockIdx.x * 32;
    int k0 = kc * 384;
    __shared__ float As[16][64];
    __shared__ float Bs[16][32];
    int tid = threadIdx.x;
    int tm = (tid >> 3) * 2;
    int tn = (tid & 7) * 4;
    ull acc[2][2] = {{0ull,0ull},{0ull,0ull}};

    for (int kb = 0; kb < 384; kb += 16) {
#pragma unroll
        for (int u = 0; u < 4; u++) {
            int e = tid + 256*u;
            int m = e & 63, kl = e >> 6;
            int kg = k0 + kb + kl;
            float av = (kg < HH) ? g_hbuf[m*HH + kg] : g_ctxbuf[m*MD + (kg - HH)];
            As[kl][m] = av;
        }
#pragma unroll
        for (int u = 0; u < 2; u++) {
            int e = tid + 256*u;
            int n = e & 31, kl = e >> 5;
            int kg = k0 + kb + kl;
            Bs[kl][n] = Wa[(size_t)kg*HH + bn + n];
        }
        __syncthreads();
#pragma unroll
        for (int k = 0; k < 16; k++) {
            float a0 = As[k][tm], a1 = As[k][tm+1];
            float4 b4 = *(const float4*)&Bs[k][tn];
            ull bp0 = pack2(b4.x, b4.y), bp1 = pack2(b4.z, b4.w);
            ull a20 = pack2(a0, a0), a21 = pack2(a1, a1);
            acc[0][0] = fma2(a20, bp0, acc[0][0]);
            acc[0][1] = fma2(a20, bp1, acc[0][1]);
            acc[1][0] = fma2(a21, bp0, acc[1][0]);
            acc[1][1] = fma2(a21, bp1, acc[1][1]);
        }
        __syncthreads();
    }
    float* pa = g_pa + (size_t)(t*4 + kc) * BH;
#pragma unroll
    for (int i = 0; i < 2; i++) {
        float2 v0 = unpack2(acc[i][0]), v1 = unpack2(acc[i][1]);
        float4 o; o.x = v0.x; o.y = v0.y; o.z = v1.x; o.w = v1.y;
        *(float4*)(pa + (size_t)(tm + i)*HH + bn + tn) = o;
    }
}

// ------------- reduce all attn2 partials into [b*T+t, h] layout --------------
__global__ void k_redall() {
    int idx = blockIdx.x * blockDim.x + threadIdx.x;
    if (idx >= TT*BH) return;
    int t = idx / BH, r = idx - t*BH;
    int b = r / HH, h = r - b*HH;
    size_t base = (size_t)(t*4) * BH + r;
    float s = g_pa[base] + g_pa[base+BH] + g_pa[base+2*(size_t)BH] + g_pa[base+3*(size_t)BH];
    g_attn2all[((size_t)b*TT + t)*HH + h] = s;
}

// ------------- final logits GEMM: [1984x512] @ [512x34004] + bfc -------------
#define LBM 128
#define LBN 128
#define LBK 16
__global__ void __launch_bounds__(256, 2) k_logits(const float* __restrict__ Bw,
                                                   const float* __restrict__ bias,
                                                   float* __restrict__ C) {
    __shared__ float As[LBK][LBM + 1];
    __shared__ float Bs[LBK][LBN];
    int bm = blockIdx.y * LBM;
    int bn = blockIdx.x * LBN;
    int tid = threadIdx.x;
    int tm  = (tid >> 4) * 8;          // 8 rows
    int tna = (tid & 15) * 4;          // two 4-col groups: tna and 64+tna
    ull acc[8][4];
#pragma unroll
    for (int i = 0; i < 8; i++)
#pragma unroll
        for (int j = 0; j < 4; j++) acc[i][j] = 0ull;

    const float* A = g_attn2all;
    for (int kb = 0; kb < HH; kb += LBK) {
        // A tile: 128 x 16
        {
            int m_l = tid >> 1, ks = (tid & 1) * 8;
            int gm = bm + m_l;
            float4 a0, a1;
            if (gm < BB*TT) {
                const float4* ap = (const float4*)(A + (size_t)gm*HH + kb + ks);
                a0 = ap[0]; a1 = ap[1];
            } else {
                a0 = make_float4(0,0,0,0); a1 = a0;
            }
            As[ks+0][m_l]=a0.x; As[ks+1][m_l]=a0.y; As[ks+2][m_l]=a0.z; As[ks+3][m_l]=a0.w;
            As[ks+4][m_l]=a1.x; As[ks+5][m_l]=a1.y; As[ks+6][m_l]=a1.z; As[ks+7][m_l]=a1.w;
        }
        // B tile: 16 x 128
#pragma unroll
        for (int u = 0; u < 2; u++) {
            int idx = tid + 256*u;            // 0..511 in float4 units
            int kl = idx >> 5, c4 = (idx & 31) * 4;
            int gn = bn + c4;
            float4 bv;
            const float* brow = Bw + (size_t)(kb + kl) * VV;
            if (gn + 3 < VV) {
                bv = *(const float4*)(brow + gn);
            } else {
                bv.x = (gn+0 < VV) ? brow[gn+0] : 0.f;
                bv.y = (gn+1 < VV) ? brow[gn+1] : 0.f;
                bv.z = (gn+2 < VV) ? brow[gn+2] : 0.f;
                bv.w = (gn+3 < VV) ? brow[gn+3] : 0.f;
            }
            *(float4*)&Bs[kl][c4] = bv;
        }
        __syncthreads();
#pragma unroll
        for (int k = 0; k < LBK; k++) {
            float a[8];
#pragma unroll
            for (int i = 0; i < 8; i++) a[i] = As[k][tm + i];
            float4 b0 = *(const float4*)&Bs[k][tna];
            float4 b1 = *(const float4*)&Bs[k][64 + tna];
            ull bp[4];
            bp[0] = pack2(b0.x, b0.y); bp[1] = pack2(b0.z, b0.w);
            bp[2] = pack2(b1.x, b1.y); bp[3] = pack2(b1.z, b1.w);
#pragma unroll
            for (int i = 0; i < 8; i++) {
                ull a2 = pack2(a[i], a[i]);
#pragma unroll
                for (int j = 0; j < 4; j++) acc[i][j] = fma2(a2, bp[j], acc[i][j]);
            }
        }
        __syncthreads();
    }
    // epilogue
    int coln[4] = {tna, tna + 2, 64 + tna, 64 + tna + 2};
#pragma unroll
    for (int i = 0; i < 8; i++) {
        int gm = bm + tm + i;
        if (gm >= BB*TT) continue;
#pragma unroll
        for (int j = 0; j < 4; j++) {
            float2 v = unpack2(acc[i][j]);
            int gn = bn + coln[j];
            if (gn < VV)     C[(size_t)gm*VV + gn]     = v.x + bias[gn];
            if (gn + 1 < VV) C[(size_t)gm*VV + gn + 1] = v.y + bias[gn + 1];
        }
    }
}

// ----------------------------- launch sequence -------------------------------
extern "C" void kernel_launch(void* const* d_in, const int* in_sizes, int n_in,
                              void* d_out, int out_size) {
    const void*  dec    = d_in[0];
    const float* memory = (const float*)d_in[1];
    const float* h0     = (const float*)d_in[2];
    const float* c0     = (const float*)d_in[3];
    const float* emb    = (const float*)d_in[4];
    const float* Wk     = (const float*)d_in[5];
    const float* Wr     = (const float*)d_in[6];
    const float* bb     = (const float*)d_in[7];
    const float* Wm     = (const float*)d_in[8];
    const float* Wq     = (const float*)d_in[9];
    const float* vv     = (const float*)d_in[10];
    const float* Wa     = (const float*)d_in[11];
    const float* Wfc    = (const float*)d_in[12];
    const float* bfc    = (const float*)d_in[13];
    float* out = (float*)d_out;

    k_init<<<(BB*TT*EE + 255)/256, 256>>>(dec, h0, c0, emb);
    k_keys<<<dim3(HH/64, (BB*SS)/64), 256>>>(memory, Wm);

    for (int t = 0; t < TT; t++) {
        k_lstm_z<<<dim3(Z4H/32, 3), 256>>>(Wk, Wr, t);
        k_attn<<<BB, 256>>>(memory, Wq, vv, bb);
        k_attn2<<<dim3(HH/32, 4), 256>>>(Wa, t);
    }
    k_redall<<<(TT*BH + 255)/256, 256>>>();
    k_logits<<<dim3((VV + LBN - 1)/LBN, (BB*TT + LBM - 1)/LBM), 256>>>(Wfc, bfc, out);
}

// round 3
// speedup vs baseline: 1.0059x; 1.0059x over previous
#include <cuda_runtime.h>
#include <cstdint>
#include <cstddef>

#define BB   64
#define TT   31
#define SS   32
#define VV   34004
#define EE   300
#define HH   512
#define MD   1024
#define BH   (BB*HH)          // 32768
#define Z4H  2048             // 4*H

typedef unsigned long long ull;

// ----------------------------- device scratch --------------------------------
__device__ __align__(16) float g_keys[BB*SS*HH];        // 4 MB
__device__ __align__(16) float g_x[BB*TT*EE];           // gathered embeddings
__device__ __align__(16) float g_hbuf[BH];
__device__ __align__(16) float g_cbuf[BH];
__device__ __align__(16) float g_ctxbuf[BB*MD];
__device__ __align__(16) float g_zp[3*BB*Z4H];          // 3 split-K partials of z
__device__ __align__(16) float g_pa[4*TT*BH];           // attn2 split-K partials per step
__device__ __align__(16) float g_attn2all[BB*TT*HH];    // reduced attn2, row = b*T+t

// ----------------------------- helpers ---------------------------------------
__device__ __forceinline__ ull pack2(float x, float y) {
    ull r; asm("mov.b64 %0, {%1,%2};" : "=l"(r) : "f"(x), "f"(y)); return r;
}
__device__ __forceinline__ ull fma2(ull a, ull b, ull c) {
    ull d; asm("fma.rn.f32x2 %0, %1, %2, %3;" : "=l"(d) : "l"(a), "l"(b), "l"(c)); return d;
}
__device__ __forceinline__ float2 unpack2(ull a) {
    float2 f; asm("mov.b64 {%0,%1}, %2;" : "=f"(f.x), "=f"(f.y) : "l"(a)); return f;
}

// ----------------------------- init: tokens + embedding gather ---------------
__global__ void k_init(const void* __restrict__ dec,
                       const float* __restrict__ h0,
                       const float* __restrict__ c0,
                       const float* __restrict__ emb) {
    int idx = blockIdx.x * blockDim.x + threadIdx.x;
    // Probe int64 vs int32 token storage (uniform decision, all threads agree).
    const long long* p64 = (const long long*)dec;
    bool is64 = true;
#pragma unroll
    for (int i = 0; i < 4; i++) {
        long long v = p64[i];
        if (v < 0 || v >= VV) is64 = false;
    }
    if (idx < BB*TT*EE) {
        int i = idx / EE;           // i = b*T + t
        int e = idx - i*EE;
        long long tok = is64 ? p64[i] : (long long)((const int*)dec)[i];
        g_x[idx] = emb[(size_t)tok * EE + e];
    }
    if (idx < BH) {
        g_hbuf[idx] = h0[idx];
        g_cbuf[idx] = c0[idx];
    }
}

// ----------------------------- keys GEMM: [2048x1024]@[1024x512] -------------
__global__ void __launch_bounds__(256) k_keys(const float* __restrict__ memory,
                                              const float* __restrict__ Wm) {
    __shared__ float As[16][65];
    __shared__ float Bs[16][64];
    int bm = blockIdx.y * 64;
    int bn = blockIdx.x * 64;
    int tid = threadIdx.x;
    int tm = (tid >> 4) * 4;
    int tn = (tid & 15) * 4;
    ull acc[4][2];
#pragma unroll
    for (int i = 0; i < 4; i++) { acc[i][0] = 0ull; acc[i][1] = 0ull; }

    for (int kb = 0; kb < MD; kb += 16) {
        int m  = tid >> 2, ks = (tid & 3) * 4;
        float4 a4 = *(const float4*)(memory + (size_t)(bm + m) * MD + kb + ks);
        As[ks+0][m] = a4.x; As[ks+1][m] = a4.y; As[ks+2][m] = a4.z; As[ks+3][m] = a4.w;
        int kl = tid >> 4, c = (tid & 15) * 4;
        *(float4*)&Bs[kl][c] = *(const float4*)(Wm + (size_t)(kb + kl) * HH + bn + c);
        __syncthreads();
#pragma unroll
        for (int k = 0; k < 16; k++) {
            float a0 = As[k][tm+0], a1 = As[k][tm+1], a2v = As[k][tm+2], a3 = As[k][tm+3];
            float4 bq = *(const float4*)&Bs[k][tn];
            ull bp0 = pack2(bq.x, bq.y), bp1 = pack2(bq.z, bq.w);
            ull p;
            p = pack2(a0,a0);  acc[0][0]=fma2(p,bp0,acc[0][0]); acc[0][1]=fma2(p,bp1,acc[0][1]);
            p = pack2(a1,a1);  acc[1][0]=fma2(p,bp0,acc[1][0]); acc[1][1]=fma2(p,bp1,acc[1][1]);
            p = pack2(a2v,a2v);acc[2][0]=fma2(p,bp0,acc[2][0]); acc[2][1]=fma2(p,bp1,acc[2][1]);
            p = pack2(a3,a3);  acc[3][0]=fma2(p,bp0,acc[3][0]); acc[3][1]=fma2(p,bp1,acc[3][1]);
        }
        __syncthreads();
    }
#pragma unroll
    for (int i = 0; i < 4; i++) {
        float2 v0 = unpack2(acc[i][0]), v1 = unpack2(acc[i][1]);
        float4 o; o.x = v0.x; o.y = v0.y; o.z = v1.x; o.w = v1.y;
        *(float4*)(g_keys + (size_t)(bm + tm + i) * HH + bn + tn) = o;
    }
}

// ----------------------------- LSTM z partials (3-way split-K) ---------------
// split 0: x(300)@Wk[0:300]      split 1: attn_prev(512)@Wk[300:812]
// split 2: h(512)@Wr
__global__ void __launch_bounds__(256) k_lstm_z(const float* __restrict__ Wk,
                                                const float* __restrict__ Wr,
                                                int t) {
    int split = blockIdx.y;
    int bn = blockIdx.x * 32;
    int K = (split == 0) ? EE : HH;
    __shared__ float As[16][64];
    __shared__ float Bs[16][32];
    int tid = threadIdx.x;
    int tm = (tid >> 3) * 2;
    int tn = (tid & 7) * 4;
    ull acc[2][2] = {{0ull,0ull},{0ull,0ull}};

    for (int kb = 0; kb < K; kb += 16) {
#pragma unroll
        for (int u = 0; u < 4; u++) {
            int e = tid + 256*u;
            int m = e & 63, kl = e >> 6;
            int k = kb + kl;
            float av = 0.f;
            if (k < K) {
                if (split == 0)      av = g_x[((size_t)m*TT + t)*EE + k];
                else if (split == 2) av = g_hbuf[m*HH + k];
                else if (t > 0) {
                    size_t base = (size_t)((t-1)*4)*BH + m*HH + k;
                    av = g_pa[base] + g_pa[base+BH] + g_pa[base+2*(size_t)BH] + g_pa[base+3*(size_t)BH];
                }
            }
            As[kl][m] = av;
        }
#pragma unroll
        for (int u = 0; u < 2; u++) {
            int e = tid + 256*u;
            int n = e & 31, kl = e >> 5;
            int k = kb + kl;
            float bv = 0.f;
            if (k < K) {
                if (split == 2)      bv = Wr[(size_t)k*Z4H + bn + n];
                else if (split == 1) bv = Wk[(size_t)(300 + k)*Z4H + bn + n];
                else                 bv = Wk[(size_t)k*Z4H + bn + n];
            }
            Bs[kl][n] = bv;
        }
        __syncthreads();
#pragma unroll
        for (int k = 0; k < 16; k++) {
            float a0 = As[k][tm], a1 = As[k][tm+1];
            float4 b4 = *(const float4*)&Bs[k][tn];
            ull bp0 = pack2(b4.x, b4.y), bp1 = pack2(b4.z, b4.w);
            ull a20 = pack2(a0, a0), a21 = pack2(a1, a1);
            acc[0][0] = fma2(a20, bp0, acc[0][0]);
            acc[0][1] = fma2(a20, bp1, acc[0][1]);
            acc[1][0] = fma2(a21, bp0, acc[1][0]);
            acc[1][1] = fma2(a21, bp1, acc[1][1]);
        }
        __syncthreads();
    }
    float* zp = g_zp + (size_t)split * BB * Z4H;
#pragma unroll
    for (int i = 0; i < 2; i++) {
        float2 v0 = unpack2(acc[i][0]), v1 = unpack2(acc[i][1]);
        float4 o; o.x = v0.x; o.y = v0.y; o.z = v1.x; o.w = v1.y;
        *(float4*)(zp + (size_t)(tm + i) * Z4H + bn + tn) = o;
    }
}

// ------------- fused gates + Bahdanau (q, score, softmax, ctx) per batch -----
__global__ void __launch_bounds__(256) k_attn(const float* __restrict__ memory,
                                              const float* __restrict__ Wq,
                                              const float* __restrict__ vvec,
                                              const float* __restrict__ bias) {
    int b = blockIdx.x;
    int tid = threadIdx.x;
    __shared__ float h2s[HH];
    __shared__ float qs[HH];
    __shared__ float vs[HH];
    __shared__ float sc[SS];

    const size_t BZ = (size_t)BB * Z4H;
    // gates
#pragma unroll
    for (int u = 0; u < 2; u++) {
        int hh = tid + 256*u;
        size_t base = (size_t)b * Z4H + hh;
        float zi = g_zp[base]            + g_zp[BZ+base]            + g_zp[2*BZ+base]            + bias[hh];
        float zf = g_zp[base+512]        + g_zp[BZ+base+512]        + g_zp[2*BZ+base+512]        + bias[hh+512];
        float zg = g_zp[base+1024]       + g_zp[BZ+base+1024]       + g_zp[2*BZ+base+1024]       + bias[hh+1024];
        float zo = g_zp[base+1536]       + g_zp[BZ+base+1536]       + g_zp[2*BZ+base+1536]       + bias[hh+1536];
        float ii = 1.f / (1.f + expf(-zi));
        float ff = 1.f / (1.f + expf(-zf));
        float oo = 1.f / (1.f + expf(-zo));
        float c2 = ff * g_cbuf[b*HH + hh] + ii * tanhf(zg);
        float h2 = oo * tanhf(c2);
        g_cbuf[b*HH + hh] = c2;
        g_hbuf[b*HH + hh] = h2;
        h2s[hh] = h2;
        vs[hh]  = vvec[hh];
    }
    __syncthreads();
    // q = h2 @ Wq
#pragma unroll
    for (int u = 0; u < 2; u++) {
        int hh = tid + 256*u;
        float s0=0.f, s1=0.f, s2=0.f, s3=0.f;
        for (int k = 0; k < HH; k += 4) {
            s0 += h2s[k+0] * Wq[(size_t)(k+0)*HH + hh];
            s1 += h2s[k+1] * Wq[(size_t)(k+1)*HH + hh];
            s2 += h2s[k+2] * Wq[(size_t)(k+2)*HH + hh];
            s3 += h2s[k+3] * Wq[(size_t)(k+3)*HH + hh];
        }
        qs[hh] = (s0+s1) + (s2+s3);
    }
    __syncthreads();
    // scores
    int w = tid >> 5, lane = tid & 31;
#pragma unroll
    for (int si = 0; si < 4; si++) {
        int s = w*4 + si;
        const float* kp = g_keys + ((size_t)(b*SS + s)) * HH;
        float acc = 0.f;
        for (int h = lane; h < HH; h += 32)
            acc += tanhf(kp[h] + qs[h]) * vs[h];
#pragma unroll
        for (int off = 16; off; off >>= 1)
            acc += __shfl_down_sync(0xffffffffu, acc, off);
        if (lane == 0) sc[s] = acc;
    }
    __syncthreads();
    // softmax over 32 (warp 0)
    if (tid < 32) {
        float x = sc[tid];
        float mx = x;
#pragma unroll
        for (int off = 16; off; off >>= 1) mx = fmaxf(mx, __shfl_xor_sync(0xffffffffu, mx, off));
        float e = expf(x - mx);
        float sm = e;
#pragma unroll
        for (int off = 16; off; off >>= 1) sm += __shfl_xor_sync(0xffffffffu, sm, off);
        sc[tid] = e / sm;
    }
    __syncthreads();
    // ctx = al @ memory[b]
    const float* mp = memory + (size_t)b * SS * MD;
#pragma unroll
    for (int u = 0; u < 4; u++) {
        int m = tid + 256*u;
        float acc = 0.f;
#pragma unroll
        for (int s = 0; s < SS; s++) acc += sc[s] * mp[(size_t)s*MD + m];
        g_ctxbuf[b*MD + m] = acc;
    }
}

// ------------- attn2 partials: concat(h2,ctx)[64x1536] @ Wa[1536x512], splitK4
__global__ void __launch_bounds__(256) k_attn2(const float* __restrict__ Wa, int t) {
    int kc = blockIdx.y;                // K chunk of 384
    int bn = blockIdx.x * 32;
    int k0 = kc * 384;
    __shared__ float As[16][64];
    __shared__ float Bs[16][32];
    int tid = threadIdx.x;
    int tm = (tid >> 3) * 2;
    int tn = (tid & 7) * 4;
    ull acc[2][2] = {{0ull,0ull},{0ull,0ull}};

    for (int kb = 0; kb < 384; kb += 16) {
#pragma unroll
        for (int u = 0; u < 4; u++) {
            int e = tid + 256*u;
            int m = e & 63, kl = e >> 6;
            int kg = k0 + kb + kl;
            float av = (kg < HH) ? g_hbuf[m*HH + kg] : g_ctxbuf[m*MD + (kg - HH)];
            As[kl][m] = av;
        }
#pragma unroll
        for (int u = 0; u < 2; u++) {
            int e = tid + 256*u;
            int n = e & 31, kl = e >> 5;
            int kg = k0 + kb + kl;
            Bs[kl][n] = Wa[(size_t)kg*HH + bn + n];
        }
        __syncthreads();
#pragma unroll
        for (int k = 0; k < 16; k++) {
            float a0 = As[k][tm], a1 = As[k][tm+1];
            float4 b4 = *(const float4*)&Bs[k][tn];
            ull bp0 = pack2(b4.x, b4.y), bp1 = pack2(b4.z, b4.w);
            ull a20 = pack2(a0, a0), a21 = pack2(a1, a1);
            acc[0][0] = fma2(a20, bp0, acc[0][0]);
            acc[0][1] = fma2(a20, bp1, acc[0][1]);
            acc[1][0] = fma2(a21, bp0, acc[1][0]);
            acc[1][1] = fma2(a21, bp1, acc[1][1]);
        }
        __syncthreads();
    }
    float* pa = g_pa + (size_t)(t*4 + kc) * BH;
#pragma unroll
    for (int i = 0; i < 2; i++) {
        float2 v0 = unpack2(acc[i][0]), v1 = unpack2(acc[i][1]);
        float4 o; o.x = v0.x; o.y = v0.y; o.z = v1.x; o.w = v1.y;
        *(float4*)(pa + (size_t)(tm + i)*HH + bn + tn) = o;
    }
}

// ------------- reduce all attn2 partials into [b*T+t, h] layout --------------
__global__ void k_redall() {
    int idx = blockIdx.x * blockDim.x + threadIdx.x;
    if (idx >= TT*BH) return;
    int t = idx / BH, r = idx - t*BH;
    int b = r / HH, h = r - b*HH;
    size_t base = (size_t)(t*4) * BH + r;
    float s = g_pa[base] + g_pa[base+BH] + g_pa[base+2*(size_t)BH] + g_pa[base+3*(size_t)BH];
    g_attn2all[((size_t)b*TT + t)*HH + h] = s;
}

// ------------- final logits GEMM: [1984x512] @ [512x34004] + bfc -------------
#define LBM 128
#define LBN 128
#define LBK 16
__global__ void __launch_bounds__(256, 2) k_logits(const float* __restrict__ Bw,
                                                   const float* __restrict__ bias,
                                                   float* __restrict__ C) {
    __shared__ float As[LBK][LBM + 1];
    __shared__ float Bs[LBK][LBN];
    int bm = blockIdx.y * LBM;
    int bn = blockIdx.x * LBN;
    int tid = threadIdx.x;
    int tm  = (tid >> 4) * 8;          // 8 rows
    int tna = (tid & 15) * 4;          // two 4-col groups: tna and 64+tna
    ull acc[8][4];
#pragma unroll
    for (int i = 0; i < 8; i++)
#pragma unroll
        for (int j = 0; j < 4; j++) acc[i][j] = 0ull;

    const float* A = g_attn2all;
    for (int kb = 0; kb < HH; kb += LBK) {
        // A tile: 128 x 16
        {
            int m_l = tid >> 1, ks = (tid & 1) * 8;
            int gm = bm + m_l;
            float4 a0, a1;
            if (gm < BB*TT) {
                const float4* ap = (const float4*)(A + (size_t)gm*HH + kb + ks);
                a0 = ap[0]; a1 = ap[1];
            } else {
                a0 = make_float4(0,0,0,0); a1 = a0;
            }
            As[ks+0][m_l]=a0.x; As[ks+1][m_l]=a0.y; As[ks+2][m_l]=a0.z; As[ks+3][m_l]=a0.w;
            As[ks+4][m_l]=a1.x; As[ks+5][m_l]=a1.y; As[ks+6][m_l]=a1.z; As[ks+7][m_l]=a1.w;
        }
        // B tile: 16 x 128
#pragma unroll
        for (int u = 0; u < 2; u++) {
            int idx = tid + 256*u;            // 0..511 in float4 units
            int kl = idx >> 5, c4 = (idx & 31) * 4;
            int gn = bn + c4;
            float4 bv;
            const float* brow = Bw + (size_t)(kb + kl) * VV;
            if (gn + 3 < VV) {
                bv = *(const float4*)(brow + gn);
            } else {
                bv.x = (gn+0 < VV) ? brow[gn+0] : 0.f;
                bv.y = (gn+1 < VV) ? brow[gn+1] : 0.f;
                bv.z = (gn+2 < VV) ? brow[gn+2] : 0.f;
                bv.w = (gn+3 < VV) ? brow[gn+3] : 0.f;
            }
            *(float4*)&Bs[kl][c4] = bv;
        }
        __syncthreads();
#pragma unroll
        for (int k = 0; k < LBK; k++) {
            float a[8];
#pragma unroll
            for (int i = 0; i < 8; i++) a[i] = As[k][tm + i];
            float4 b0 = *(const float4*)&Bs[k][tna];
            float4 b1 = *(const float4*)&Bs[k][64 + tna];
            ull bp[4];
            bp[0] = pack2(b0.x, b0.y); bp[1] = pack2(b0.z, b0.w);
            bp[2] = pack2(b1.x, b1.y); bp[3] = pack2(b1.z, b1.w);
#pragma unroll
            for (int i = 0; i < 8; i++) {
                ull a2 = pack2(a[i], a[i]);
#pragma unroll
                for (int j = 0; j < 4; j++) acc[i][j] = fma2(a2, bp[j], acc[i][j]);
            }
        }
        __syncthreads();
    }
    // epilogue
    int coln[4] = {tna, tna + 2, 64 + tna, 64 + tna + 2};
#pragma unroll
    for (int i = 0; i < 8; i++) {
        int gm = bm + tm + i;
        if (gm >= BB*TT) continue;
#pragma unroll
        for (int j = 0; j < 4; j++) {
            float2 v = unpack2(acc[i][j]);
            int gn = bn + coln[j];
            if (gn < VV)     C[(size_t)gm*VV + gn]     = v.x + bias[gn];
            if (gn + 1 < VV) C[(size_t)gm*VV + gn + 1] = v.y + bias[gn + 1];
        }
    }
}

// ----------------------------- launch sequence -------------------------------
extern "C" void kernel_launch(void* const* d_in, const int* in_sizes, int n_in,
                              void* d_out, int out_size) {
    const void*  dec    = d_in[0];
    const float* memory = (const float*)d_in[1];
    const float* h0     = (const float*)d_in[2];
    const float* c0     = (const float*)d_in[3];
    const float* emb    = (const float*)d_in[4];
    const float* Wk     = (const float*)d_in[5];
    const float* Wr     = (const float*)d_in[6];
    const float* bb     = (const float*)d_in[7];
    const float* Wm     = (const float*)d_in[8];
    const float* Wq     = (const float*)d_in[9];
    const float* vv     = (const float*)d_in[10];
    const float* Wa     = (const float*)d_in[11];
    const float* Wfc    = (const float*)d_in[12];
    const float* bfc    = (const float*)d_in[13];
    float* out = (float*)d_out;

    k_init<<<(BB*TT*EE + 255)/256, 256>>>(dec, h0, c0, emb);
    k_keys<<<dim3(HH/64, (BB*SS)/64), 256>>>(memory, Wm);

    for (int t = 0; t < TT; t++) {
        k_lstm_z<<<dim3(Z4H/32, 3), 256>>>(Wk, Wr, t);
        k_attn<<<BB, 256>>>(memory, Wq, vv, bb);
        k_attn2<<<dim3(HH/32, 4), 256>>>(Wa, t);
    }
    k_redall<<<(TT*BH + 255)/256, 256>>>();
    k_logits<<<dim3((VV + LBN - 1)/LBN, (BB*TT + LBM - 1)/LBM), 256>>>(Wfc, bfc, out);
}

// round 4
// speedup vs baseline: 1.8454x; 1.8347x over previous
#include <cuda_runtime.h>
#include <cstdint>
#include <cstddef>

#define BB 64
#define TT 31
#define SS 32
#define VV 34004
#define EE 300
#define HH 512
#define MD 1024
#define BH (BB*HH)
#define Z4H 2048
#define NBLK 128

typedef unsigned long long ull;

// ----------------------------- device scratch --------------------------------
__device__ __align__(16) float g_keys[BB*SS*HH];       // 4 MB
__device__ __align__(16) float g_P[BB*SS*HH];          // 4 MB  memory @ Wa_bot
__device__ __align__(16) float g_x[BB*TT*EE];          // rows r = t*64+b
__device__ __align__(16) float g_zx[BB*TT*Z4H];        // 16 MB x@Wk[:300]+bias
__device__ __align__(16) float g_W2T[Z4H*1024];        // 8 MB [n][k] k: aprev(512)|h(512)
__device__ __align__(16) float g_WqT[HH*HH];           // [n][k]
__device__ __align__(16) float g_WaT[HH*HH];           // Wa top rows, [n][k]
__device__ __align__(16) float g_h[2][BH];
__device__ __align__(16) float g_c[BH];
__device__ __align__(16) float g_aprev[BH];
__device__ __align__(16) float g_q[BH];
__device__ __align__(16) float g_score[BB*SS];
__device__ __align__(16) float g_ctxa[BH];
__device__ __align__(16) float g_attn2all[BB*TT*HH];   // rows b*TT+t
__device__ unsigned g_cnt;
__device__ unsigned g_gen;

// ----------------------------- helpers ---------------------------------------
__device__ __forceinline__ ull pack2(float x, float y) {
    ull r; asm("mov.b64 %0, {%1,%2};" : "=l"(r) : "f"(x), "f"(y)); return r;
}
__device__ __forceinline__ ull fma2(ull a, ull b, ull c) {
    ull d; asm("fma.rn.f32x2 %0, %1, %2, %3;" : "=l"(d) : "l"(a), "l"(b), "l"(c)); return d;
}
__device__ __forceinline__ float2 unpack2(ull a) {
    float2 f; asm("mov.b64 {%0,%1}, %2;" : "=f"(f.x), "=f"(f.y) : "l"(a)); return f;
}
__device__ __forceinline__ float tanh_a(float x) {
    float y; asm("tanh.approx.f32 %0, %1;" : "=f"(y) : "f"(x)); return y;
}

__device__ __forceinline__ void gbar() {
    __syncthreads();
    if (threadIdx.x == 0) {
        __threadfence();
        unsigned g = ((volatile unsigned*)&g_gen)[0];
        if (atomicAdd(&g_cnt, 1u) == NBLK - 1) {
            g_cnt = 0;
            __threadfence();
            atomicExch(&g_gen, g + 1);
        } else {
            while (((volatile unsigned*)&g_gen)[0] == g) { }
            __threadfence();
        }
    }
    __syncthreads();
}

// ----------------------------- init -------------------------------------------
__global__ void k_init(const void* __restrict__ dec,
                       const float* __restrict__ h0,
                       const float* __restrict__ c0,
                       const float* __restrict__ emb) {
    int idx = blockIdx.x * blockDim.x + threadIdx.x;
    const long long* p64 = (const long long*)dec;
    bool is64 = true;
#pragma unroll
    for (int i = 0; i < 4; i++) { long long v = p64[i]; if (v < 0 || v >= VV) is64 = false; }
    if (idx < BB*TT*EE) {
        int i = idx / EE, e = idx - i*EE;       // i = b*TT + t
        int b = i / TT, t = i - b*TT;
        long long tok = is64 ? p64[i] : (long long)((const int*)dec)[i];
        g_x[((size_t)(t*BB + b))*EE + e] = emb[(size_t)tok * EE + e];
    }
    if (idx < BH) { g_h[0][idx] = h0[idx]; g_c[idx] = c0[idx]; g_aprev[idx] = 0.f; }
    if (idx == 0) { g_cnt = 0; g_gen = 0; }
}

// ----------------------------- weight transposes ------------------------------
__global__ void k_tw(const float* __restrict__ Wk, const float* __restrict__ Wr,
                     const float* __restrict__ Wq, const float* __restrict__ Wa) {
    int idx = blockIdx.x * blockDim.x + threadIdx.x;
    const int T1 = Z4H * 1024;
    if (idx < T1) {
        int n = idx >> 10, k = idx & 1023;
        g_W2T[idx] = (k < HH) ? Wk[(size_t)(300 + k)*Z4H + n] : Wr[(size_t)(k - HH)*Z4H + n];
    } else {
        int r = idx - T1;
        if (r < HH*HH) { int n = r >> 9, k = r & 511; g_WqT[r] = Wq[(size_t)k*HH + n]; }
        else {
            r -= HH*HH;
            if (r < HH*HH) { int n = r >> 9, k = r & 511; g_WaT[r] = Wa[(size_t)k*HH + n]; }
        }
    }
}

// --------------- generic GEMM out[2048][512] = A[2048][1024] @ B[1024][512] ---
__global__ void __launch_bounds__(256) k_kp(const float* __restrict__ A,
                                            const float* __restrict__ Bm,
                                            int sel) {
    __shared__ float As[16][65];
    __shared__ float Bsh[16][64];
    float* outp = sel ? g_P : g_keys;
    int bm = blockIdx.y * 64, bn = blockIdx.x * 64;
    int tid = threadIdx.x;
    int tm = (tid >> 4) * 4, tn = (tid & 15) * 4;
    ull acc[4][2];
#pragma unroll
    for (int i = 0; i < 4; i++) { acc[i][0] = 0ull; acc[i][1] = 0ull; }
    for (int kb = 0; kb < MD; kb += 16) {
        int m = tid >> 2, ks = (tid & 3) * 4;
        float4 a4 = *(const float4*)(A + (size_t)(bm + m)*MD + kb + ks);
        As[ks+0][m] = a4.x; As[ks+1][m] = a4.y; As[ks+2][m] = a4.z; As[ks+3][m] = a4.w;
        int kl = tid >> 4, c = (tid & 15) * 4;
        *(float4*)&Bsh[kl][c] = *(const float4*)(Bm + (size_t)(kb + kl)*HH + bn + c);
        __syncthreads();
#pragma unroll
        for (int k = 0; k < 16; k++) {
            float4 bq = *(const float4*)&Bsh[k][tn];
            ull bp0 = pack2(bq.x, bq.y), bp1 = pack2(bq.z, bq.w);
#pragma unroll
            for (int i = 0; i < 4; i++) {
                float a = As[k][tm + i];
                ull p = pack2(a, a);
                acc[i][0] = fma2(p, bp0, acc[i][0]);
                acc[i][1] = fma2(p, bp1, acc[i][1]);
            }
        }
        __syncthreads();
    }
#pragma unroll
    for (int i = 0; i < 4; i++) {
        float2 v0 = unpack2(acc[i][0]), v1 = unpack2(acc[i][1]);
        float4 o; o.x = v0.x; o.y = v0.y; o.z = v1.x; o.w = v1.y;
        *(float4*)(outp + (size_t)(bm + tm + i)*HH + bn + tn) = o;
    }
}

// --------------- zx = x @ Wk[0:300] + bias : [1984][2048] ---------------------
__global__ void __launch_bounds__(256) k_zx(const float* __restrict__ Wk,
                                            const float* __restrict__ bb) {
    __shared__ float As[16][65];
    __shared__ float Bsh[16][64];
    int bm = blockIdx.y * 64, bn = blockIdx.x * 64;
    int tid = threadIdx.x;
    int tm = (tid >> 4) * 4, tn = (tid & 15) * 4;
    ull acc[4][2];
#pragma unroll
    for (int i = 0; i < 4; i++) { acc[i][0] = 0ull; acc[i][1] = 0ull; }
    for (int kb = 0; kb < EE; kb += 16) {
        int m = tid >> 2, ks = (tid & 3) * 4;
        float4 a4 = make_float4(0.f, 0.f, 0.f, 0.f);
        if (kb + ks < EE) a4 = *(const float4*)(g_x + (size_t)(bm + m)*EE + kb + ks);
        As[ks+0][m] = a4.x; As[ks+1][m] = a4.y; As[ks+2][m] = a4.z; As[ks+3][m] = a4.w;
        int kl = tid >> 4, c = (tid & 15) * 4;
        float4 b4 = make_float4(0.f, 0.f, 0.f, 0.f);
        if (kb + kl < EE) b4 = *(const float4*)(Wk + (size_t)(kb + kl)*Z4H + bn + c);
        *(float4*)&Bsh[kl][c] = b4;
        __syncthreads();
#pragma unroll
        for (int k = 0; k < 16; k++) {
            float4 bq = *(const float4*)&Bsh[k][tn];
            ull bp0 = pack2(bq.x, bq.y), bp1 = pack2(bq.z, bq.w);
#pragma unroll
            for (int i = 0; i < 4; i++) {
                float a = As[k][tm + i];
                ull p = pack2(a, a);
                acc[i][0] = fma2(p, bp0, acc[i][0]);
                acc[i][1] = fma2(p, bp1, acc[i][1]);
            }
        }
        __syncthreads();
    }
#pragma unroll
    for (int i = 0; i < 4; i++) {
        float2 v0 = unpack2(acc[i][0]), v1 = unpack2(acc[i][1]);
        float4 o;
        o.x = v0.x + bb[bn + tn + 0]; o.y = v0.y + bb[bn + tn + 1];
        o.z = v1.x + bb[bn + tn + 2]; o.w = v1.y + bb[bn + tn + 3];
        *(float4*)(g_zx + (size_t)(bm + tm + i)*Z4H + bn + tn) = o;
    }
}

// ----------------------------- persistent recurrence --------------------------
__global__ void __launch_bounds__(256, 1) k_loop(const float* __restrict__ vvec) {
    __shared__ float As[64][65];      // also h2 tile for phases B/E
    __shared__ ull   Bs2[8][64];
    __shared__ float Bq[4][64];
    __shared__ float qs[HH];
    __shared__ float vs[HH];
    __shared__ float sc2[SS];
    __shared__ float al2[SS];

    const int j = blockIdx.x;
    const int tid = threadIdx.x;
    const int m  = tid & 63;
    const int hq = tid >> 6;          // 0..3
    const int nq = tid >> 6;

    for (int t = 0; t < TT; t++) {
        const int cur = t & 1, nxt = cur ^ 1;

        // ---------------- phase A: z GEMM (K=1024) + gates ----------------
        {
            ull acc0 = 0ull, acc1 = 0ull;
            const int base = (j << 2);
            for (int kb = 0; kb < 1024; kb += 64) {
#pragma unroll
                for (int u = 0; u < 4; u++) {
                    int e = tid + 256*u;
                    int mm = e & 63, kq = e >> 6;     // kq 0..15
                    int kk = kb + kq*4;
                    float4 v = (kk < 512)
                        ? *(const float4*)(g_aprev + (size_t)mm*HH + kk)
                        : *(const float4*)(&g_h[cur][(size_t)mm*HH + kk - 512]);
                    As[kq*4+0][mm] = v.x; As[kq*4+1][mm] = v.y;
                    As[kq*4+2][mm] = v.z; As[kq*4+3][mm] = v.w;
                }
#pragma unroll
                for (int u = 0; u < 2; u++) {
                    int e = tid + 256*u;
                    int pr = e >> 6, k = e & 63;      // pr = gp*4+hq2
                    int gp = pr >> 2, hq2 = pr & 3;
                    const float* w0 = g_W2T + (size_t)((gp*2)*HH + base + hq2)*1024 + kb + k;
                    float f0 = w0[0];
                    float f1 = w0[(size_t)HH*1024];
                    Bs2[pr][k] = pack2(f0, f1);
                }
                __syncthreads();
#pragma unroll 8
                for (int k = 0; k < 64; k++) {
                    float a = As[k][m];
                    ull a2 = pack2(a, a);
                    acc0 = fma2(a2, Bs2[hq][k],     acc0);
                    acc1 = fma2(a2, Bs2[4 + hq][k], acc1);
                }
                __syncthreads();
            }
            int h = base + hq;
            float2 v0 = unpack2(acc0);   // (i, f)
            float2 v1 = unpack2(acc1);   // (g, o)
            size_t zr = (size_t)(t*BB + m)*Z4H;
            float zi = v0.x + g_zx[zr + h];
            float zf = v0.y + g_zx[zr + 512 + h];
            float zg = v1.x + g_zx[zr + 1024 + h];
            float zo = v1.y + g_zx[zr + 1536 + h];
            float ii = 1.f/(1.f + expf(-zi));
            float ff = 1.f/(1.f + expf(-zf));
            float oo = 1.f/(1.f + expf(-zo));
            float c2 = ff*g_c[m*HH + h] + ii*tanhf(zg);
            float h2 = oo*tanhf(c2);
            g_c[m*HH + h] = c2;
            g_h[nxt][m*HH + h] = h2;
        }
        gbar();

        // ---------------- phase B: q = h2 @ WqT ---------------------------
        {
            const int n0 = j << 2;
            float acc = 0.f;
            for (int kb = 0; kb < HH; kb += 64) {
#pragma unroll
                for (int u = 0; u < 4; u++) {
                    int e = tid + 256*u;
                    int mm = e & 63, kq = e >> 6;
                    float4 v = *(const float4*)(&g_h[nxt][(size_t)mm*HH + kb + kq*4]);
                    As[kq*4+0][mm] = v.x; As[kq*4+1][mm] = v.y;
                    As[kq*4+2][mm] = v.z; As[kq*4+3][mm] = v.w;
                }
                if (tid < 64) {
                    int n = tid >> 4, k4 = (tid & 15)*4;
                    *(float4*)&Bq[n][k4] = *(const float4*)(g_WqT + (size_t)(n0 + n)*HH + kb + k4);
                }
                __syncthreads();
#pragma unroll 16
                for (int k = 0; k < 64; k++) acc += As[k][m] * Bq[nq][k];
                __syncthreads();
            }
            g_q[m*HH + n0 + nq] = acc;
        }
        gbar();

        // ---------------- phase C: scores --------------------------------
        {
            int b = j >> 1, sh = (j & 1) * 16;
            for (int i = tid; i < HH; i += 256) { qs[i] = g_q[b*HH + i]; vs[i] = vvec[i]; }
            __syncthreads();
            int w = tid >> 5, lane = tid & 31;
#pragma unroll
            for (int si = 0; si < 2; si++) {
                int s = sh + (w << 1) + si;
                const float* kp = g_keys + (size_t)(b*SS + s)*HH;
                float acc = 0.f;
                for (int h = lane; h < HH; h += 32)
                    acc += tanh_a(kp[h] + qs[h]) * vs[h];
#pragma unroll
                for (int off = 16; off; off >>= 1)
                    acc += __shfl_down_sync(0xffffffffu, acc, off);
                if (lane == 0) g_score[b*SS + s] = acc;
            }
            __syncthreads();
        }
        gbar();

        // ---------------- phase D: softmax + ctx part (64 blocks) --------
        if (j < BB) {
            int b = j;
            if (tid < SS) sc2[tid] = g_score[b*SS + tid];
            __syncthreads();
            if (tid < SS) {
                float x = sc2[tid];
                float mx = x;
#pragma unroll
                for (int off = 16; off; off >>= 1) mx = fmaxf(mx, __shfl_xor_sync(0xffffffffu, mx, off));
                float e = expf(x - mx);
                float sm = e;
#pragma unroll
                for (int off = 16; off; off >>= 1) sm += __shfl_xor_sync(0xffffffffu, sm, off);
                al2[tid] = e / sm;
            }
            __syncthreads();
            for (int n = tid; n < HH; n += 256) {
                float acc = 0.f;
#pragma unroll
                for (int s = 0; s < SS; s++)
                    acc += al2[s] * g_P[(size_t)(b*SS + s)*HH + n];
                g_ctxa[b*HH + n] = acc;
            }
        }
        gbar();

        // ---------------- phase E: attn2 = h2@WaT + ctxa -----------------
        {
            const int n0 = j << 2;
            float acc = 0.f;
            for (int kb = 0; kb < HH; kb += 64) {
#pragma unroll
                for (int u = 0; u < 4; u++) {
                    int e = tid + 256*u;
                    int mm = e & 63, kq = e >> 6;
                    float4 v = *(const float4*)(&g_h[nxt][(size_t)mm*HH + kb + kq*4]);
                    As[kq*4+0][mm] = v.x; As[kq*4+1][mm] = v.y;
                    As[kq*4+2][mm] = v.z; As[kq*4+3][mm] = v.w;
                }
                if (tid < 64) {
                    int n = tid >> 4, k4 = (tid & 15)*4;
                    *(float4*)&Bq[n][k4] = *(const float4*)(g_WaT + (size_t)(n0 + n)*HH + kb + k4);
                }
                __syncthreads();
#pragma unroll 16
                for (int k = 0; k < 64; k++) acc += As[k][m] * Bq[nq][k];
                __syncthreads();
            }
            int nc = n0 + nq;
            float val = acc + g_ctxa[m*HH + nc];
            g_aprev[m*HH + nc] = val;
            g_attn2all[((size_t)m*TT + t)*HH + nc] = val;
        }
        if (t < TT - 1) gbar();
    }
}

// ------------- final logits GEMM: [1984x512] @ [512x34004] + bfc --------------
#define LBM 128
#define LBN 128
#define LBK 16
__global__ void __launch_bounds__(256, 2) k_logits(const float* __restrict__ Bw,
                                                   const float* __restrict__ bias,
                                                   float* __restrict__ C) {
    __shared__ float As[LBK][LBM + 1];
    __shared__ float Bs[LBK][LBN];
    int bm = blockIdx.y * LBM;
    int bn = blockIdx.x * LBN;
    int tid = threadIdx.x;
    int tm  = (tid >> 4) * 8;
    int tna = (tid & 15) * 4;
    ull acc[8][4];
#pragma unroll
    for (int i = 0; i < 8; i++)
#pragma unroll
        for (int jj = 0; jj < 4; jj++) acc[i][jj] = 0ull;

    const float* A = g_attn2all;
    for (int kb = 0; kb < HH; kb += LBK) {
        {
            int m_l = tid >> 1, ks = (tid & 1) * 8;
            int gm = bm + m_l;
            float4 a0, a1;
            if (gm < BB*TT) {
                const float4* ap = (const float4*)(A + (size_t)gm*HH + kb + ks);
                a0 = ap[0]; a1 = ap[1];
            } else { a0 = make_float4(0,0,0,0); a1 = a0; }
            As[ks+0][m_l]=a0.x; As[ks+1][m_l]=a0.y; As[ks+2][m_l]=a0.z; As[ks+3][m_l]=a0.w;
            As[ks+4][m_l]=a1.x; As[ks+5][m_l]=a1.y; As[ks+6][m_l]=a1.z; As[ks+7][m_l]=a1.w;
        }
#pragma unroll
        for (int u = 0; u < 2; u++) {
            int idx = tid + 256*u;
            int kl = idx >> 5, c4 = (idx & 31) * 4;
            int gn = bn + c4;
            float4 bv;
            const float* brow = Bw + (size_t)(kb + kl) * VV;
            if (gn + 3 < VV) bv = *(const float4*)(brow + gn);
            else {
                bv.x = (gn+0 < VV) ? brow[gn+0] : 0.f;
                bv.y = (gn+1 < VV) ? brow[gn+1] : 0.f;
                bv.z = (gn+2 < VV) ? brow[gn+2] : 0.f;
                bv.w = (gn+3 < VV) ? brow[gn+3] : 0.f;
            }
            *(float4*)&Bs[kl][c4] = bv;
        }
        __syncthreads();
#pragma unroll
        for (int k = 0; k < LBK; k++) {
            float a[8];
#pragma unroll
            for (int i = 0; i < 8; i++) a[i] = As[k][tm + i];
            float4 b0 = *(const float4*)&Bs[k][tna];
            float4 b1 = *(const float4*)&Bs[k][64 + tna];
            ull bp[4];
            bp[0] = pack2(b0.x, b0.y); bp[1] = pack2(b0.z, b0.w);
            bp[2] = pack2(b1.x, b1.y); bp[3] = pack2(b1.z, b1.w);
#pragma unroll
            for (int i = 0; i < 8; i++) {
                ull a2 = pack2(a[i], a[i]);
#pragma unroll
                for (int jj = 0; jj < 4; jj++) acc[i][jj] = fma2(a2, bp[jj], acc[i][jj]);
            }
        }
        __syncthreads();
    }
    int coln[4] = {tna, tna + 2, 64 + tna, 64 + tna + 2};
#pragma unroll
    for (int i = 0; i < 8; i++) {
        int gm = bm + tm + i;
        if (gm >= BB*TT) continue;
#pragma unroll
        for (int jj = 0; jj < 4; jj++) {
            float2 v = unpack2(acc[i][jj]);
            int gn = bn + coln[jj];
            if (gn < VV)     C[(size_t)gm*VV + gn]     = v.x + bias[gn];
            if (gn + 1 < VV) C[(size_t)gm*VV + gn + 1] = v.y + bias[gn + 1];
        }
    }
}

// ----------------------------- launch sequence --------------------------------
extern "C" void kernel_launch(void* const* d_in, const int* in_sizes, int n_in,
                              void* d_out, int out_size) {
    const void*  dec    = d_in[0];
    const float* memory = (const float*)d_in[1];
    const float* h0     = (const float*)d_in[2];
    const float* c0     = (const float*)d_in[3];
    const float* emb    = (const float*)d_in[4];
    const float* Wk     = (const float*)d_in[5];
    const float* Wr     = (const float*)d_in[6];
    const float* bb     = (const float*)d_in[7];
    const float* Wm     = (const float*)d_in[8];
    const float* Wq     = (const float*)d_in[9];
    const float* vv     = (const float*)d_in[10];
    const float* Wa     = (const float*)d_in[11];
    const float* Wfc    = (const float*)d_in[12];
    const float* bfc    = (const float*)d_in[13];
    float* out = (float*)d_out;

    k_init<<<(BB*TT*EE + 255)/256, 256>>>(dec, h0, c0, emb);
    k_tw<<<(Z4H*1024 + 2*HH*HH + 255)/256, 256>>>(Wk, Wr, Wq, Wa);
    k_zx<<<dim3(Z4H/64, TT), 256>>>(Wk, bb);
    k_kp<<<dim3(HH/64, (BB*SS)/64), 256>>>(memory, Wm, 0);             // keys
    k_kp<<<dim3(HH/64, (BB*SS)/64), 256>>>(memory, Wa + HH*HH, 1);     // P
    k_loop<<<NBLK, 256>>>(vv);
    k_logits<<<dim3((VV + LBN - 1)/LBN, (BB*TT + LBM - 1)/LBM), 256>>>(Wfc, bfc, out);
}

// round 6
// speedup vs baseline: 2.2913x; 1.2416x over previous
#include <cuda_runtime.h>
#include <cuda_bf16.h>
#include <cstdint>
#include <cstddef>

#define BB 64
#define TT 31
#define SS 32
#define VV 34004
#define EE 300
#define HH 512
#define MD 1024
#define BH (BB*HH)
#define Z4H 2048
#define NBLK 128
#define NPAD 34048            // 266 * 128
#define MPAD 2048

typedef unsigned long long ull;

// ----------------------------- device scratch --------------------------------
__device__ __align__(16) float g_keys[BB*SS*HH];
__device__ __align__(16) float g_P[BB*SS*HH];
__device__ __align__(16) float g_x[BB*TT*EE];
__device__ __align__(16) float g_zx[BB*TT*Z4H];
__device__ __align__(16) float g_W2T[Z4H*1024];
__device__ __align__(16) float g_WqT[HH*HH];
__device__ __align__(16) float g_WaT[HH*HH];
__device__ __align__(16) float g_h[2][BH];
__device__ __align__(16) float g_c[BH];
__device__ __align__(16) float g_aprev[BH];
__device__ __align__(16) float g_q[BH];
__device__ __align__(16) float g_score[BB*SS];
__device__ __align__(16) float g_ctxa[BH];
__device__ __align__(16) float g_attn2all[BB*TT*HH];
__device__ __align__(16) __nv_bfloat16 g_Ah[MPAD*HH];
__device__ __align__(16) __nv_bfloat16 g_Al[MPAD*HH];
__device__ __align__(16) __nv_bfloat16 g_Bh[(size_t)NPAD*HH];
__device__ __align__(16) __nv_bfloat16 g_Bl[(size_t)NPAD*HH];
__device__ unsigned g_cnt;
__device__ unsigned g_gen;

// ----------------------------- scalar helpers --------------------------------
__device__ __forceinline__ ull pack2(float x, float y) {
    ull r; asm("mov.b64 %0, {%1,%2};" : "=l"(r) : "f"(x), "f"(y)); return r;
}
__device__ __forceinline__ ull fma2(ull a, ull b, ull c) {
    ull d; asm("fma.rn.f32x2 %0, %1, %2, %3;" : "=l"(d) : "l"(a), "l"(b), "l"(c)); return d;
}
__device__ __forceinline__ float2 unpack2(ull a) {
    float2 f; asm("mov.b64 {%0,%1}, %2;" : "=f"(f.x), "=f"(f.y) : "l"(a)); return f;
}
__device__ __forceinline__ float tanh_a(float x) {
    float y; asm("tanh.approx.f32 %0, %1;" : "=f"(y) : "f"(x)); return y;
}
__device__ __forceinline__ uint32_t smem_u32(const void* p) {
    uint32_t a;
    asm("{ .reg .u64 t; cvta.to.shared.u64 t, %1; cvt.u32.u64 %0, t; }" : "=r"(a) : "l"(p));
    return a;
}

__device__ __forceinline__ void gbar() {
    __syncthreads();
    if (threadIdx.x == 0) {
        __threadfence();
        unsigned g = ((volatile unsigned*)&g_gen)[0];
        if (atomicAdd(&g_cnt, 1u) == NBLK - 1) {
            g_cnt = 0;
            __threadfence();
            atomicExch(&g_gen, g + 1);
        } else {
            while (((volatile unsigned*)&g_gen)[0] == g) { }
            __threadfence();
        }
    }
    __syncthreads();
}

// ----------------------------- init -------------------------------------------
__global__ void k_init(const void* __restrict__ dec,
                       const float* __restrict__ h0,
                       const float* __restrict__ c0,
                       const float* __restrict__ emb) {
    int idx = blockIdx.x * blockDim.x + threadIdx.x;
    const long long* p64 = (const long long*)dec;
    bool is64 = true;
#pragma unroll
    for (int i = 0; i < 4; i++) { long long v = p64[i]; if (v < 0 || v >= VV) is64 = false; }
    if (idx < BB*TT*EE) {
        int i = idx / EE, e = idx - i*EE;       // i = b*TT + t
        int b = i / TT, t = i - b*TT;
        long long tok = is64 ? p64[i] : (long long)((const int*)dec)[i];
        g_x[((size_t)(t*BB + b))*EE + e] = emb[(size_t)tok * EE + e];
    }
    if (idx < BH) { g_h[0][idx] = h0[idx]; g_c[idx] = c0[idx]; g_aprev[idx] = 0.f; }
    if (idx == 0) { g_cnt = 0; g_gen = 0; }
}

// ----------------------------- weight transposes ------------------------------
__global__ void k_tw(const float* __restrict__ Wk, const float* __restrict__ Wr,
                     const float* __restrict__ Wq, const float* __restrict__ Wa) {
    int idx = blockIdx.x * blockDim.x + threadIdx.x;
    const int T1 = Z4H * 1024;
    if (idx < T1) {
        int n = idx >> 10, k = idx & 1023;
        g_W2T[idx] = (k < HH) ? Wk[(size_t)(300 + k)*Z4H + n] : Wr[(size_t)(k - HH)*Z4H + n];
    } else {
        int r = idx - T1;
        if (r < HH*HH) { int n = r >> 9, k = r & 511; g_WqT[r] = Wq[(size_t)k*HH + n]; }
        else {
            r -= HH*HH;
            if (r < HH*HH) { int n = r >> 9, k = r & 511; g_WaT[r] = Wa[(size_t)k*HH + n]; }
        }
    }
}

// --------------- generic GEMM out[2048][512] = A[2048][1024] @ B[1024][512] ---
__global__ void __launch_bounds__(256) k_kp(const float* __restrict__ A,
                                            const float* __restrict__ Bm,
                                            int sel) {
    __shared__ float As[16][65];
    __shared__ float Bsh[16][64];
    float* outp = sel ? g_P : g_keys;
    int bm = blockIdx.y * 64, bn = blockIdx.x * 64;
    int tid = threadIdx.x;
    int tm = (tid >> 4) * 4, tn = (tid & 15) * 4;
    ull acc[4][2];
#pragma unroll
    for (int i = 0; i < 4; i++) { acc[i][0] = 0ull; acc[i][1] = 0ull; }
    for (int kb = 0; kb < MD; kb += 16) {
        int m = tid >> 2, ks = (tid & 3) * 4;
        float4 a4 = *(const float4*)(A + (size_t)(bm + m)*MD + kb + ks);
        As[ks+0][m] = a4.x; As[ks+1][m] = a4.y; As[ks+2][m] = a4.z; As[ks+3][m] = a4.w;
        int kl = tid >> 4, c = (tid & 15) * 4;
        *(float4*)&Bsh[kl][c] = *(const float4*)(Bm + (size_t)(kb + kl)*HH + bn + c);
        __syncthreads();
#pragma unroll
        for (int k = 0; k < 16; k++) {
            float4 bq = *(const float4*)&Bsh[k][tn];
            ull bp0 = pack2(bq.x, bq.y), bp1 = pack2(bq.z, bq.w);
#pragma unroll
            for (int i = 0; i < 4; i++) {
                float a = As[k][tm + i];
                ull p = pack2(a, a);
                acc[i][0] = fma2(p, bp0, acc[i][0]);
                acc[i][1] = fma2(p, bp1, acc[i][1]);
            }
        }
        __syncthreads();
    }
#pragma unroll
    for (int i = 0; i < 4; i++) {
        float2 v0 = unpack2(acc[i][0]), v1 = unpack2(acc[i][1]);
        float4 o; o.x = v0.x; o.y = v0.y; o.z = v1.x; o.w = v1.y;
        *(float4*)(outp + (size_t)(bm + tm + i)*HH + bn + tn) = o;
    }
}

// --------------- zx = x @ Wk[0:300] + bias : [1984][2048] ---------------------
__global__ void __launch_bounds__(256) k_zx(const float* __restrict__ Wk,
                                            const float* __restrict__ bb) {
    __shared__ float As[16][65];
    __shared__ float Bsh[16][64];
    int bm = blockIdx.y * 64, bn = blockIdx.x * 64;
    int tid = threadIdx.x;
    int tm = (tid >> 4) * 4, tn = (tid & 15) * 4;
    ull acc[4][2];
#pragma unroll
    for (int i = 0; i < 4; i++) { acc[i][0] = 0ull; acc[i][1] = 0ull; }
    for (int kb = 0; kb < EE; kb += 16) {
        int m = tid >> 2, ks = (tid & 3) * 4;
        float4 a4 = make_float4(0.f, 0.f, 0.f, 0.f);
        if (kb + ks < EE) a4 = *(const float4*)(g_x + (size_t)(bm + m)*EE + kb + ks);
        As[ks+0][m] = a4.x; As[ks+1][m] = a4.y; As[ks+2][m] = a4.z; As[ks+3][m] = a4.w;
        int kl = tid >> 4, c = (tid & 15) * 4;
        float4 b4 = make_float4(0.f, 0.f, 0.f, 0.f);
        if (kb + kl < EE) b4 = *(const float4*)(Wk + (size_t)(kb + kl)*Z4H + bn + c);
        *(float4*)&Bsh[kl][c] = b4;
        __syncthreads();
#pragma unroll
        for (int k = 0; k < 16; k++) {
            float4 bq = *(const float4*)&Bsh[k][tn];
            ull bp0 = pack2(bq.x, bq.y), bp1 = pack2(bq.z, bq.w);
#pragma unroll
            for (int i = 0; i < 4; i++) {
                float a = As[k][tm + i];
                ull p = pack2(a, a);
                acc[i][0] = fma2(p, bp0, acc[i][0]);
                acc[i][1] = fma2(p, bp1, acc[i][1]);
            }
        }
        __syncthreads();
    }
#pragma unroll
    for (int i = 0; i < 4; i++) {
        float2 v0 = unpack2(acc[i][0]), v1 = unpack2(acc[i][1]);
        float4 o;
        o.x = v0.x + bb[bn + tn + 0]; o.y = v0.y + bb[bn + tn + 1];
        o.z = v1.x + bb[bn + tn + 2]; o.w = v1.y + bb[bn + tn + 3];
        *(float4*)(g_zx + (size_t)(bm + tm + i)*Z4H + bn + tn) = o;
    }
}

// ----------------------------- persistent recurrence --------------------------
__global__ void __launch_bounds__(256, 1) k_loop(const float* __restrict__ vvec) {
    __shared__ float As[64][65];
    __shared__ ull   Bs2[8][64];
    __shared__ float Bq[4][64];
    __shared__ float qs[HH];
    __shared__ float vs[HH];
    __shared__ float sc2[SS];
    __shared__ float al2[SS];

    const int j = blockIdx.x;
    const int tid = threadIdx.x;
    const int m  = tid & 63;
    const int hq = tid >> 6;
    const int nq = tid >> 6;

    for (int t = 0; t < TT; t++) {
        const int cur = t & 1, nxt = cur ^ 1;

        // phase A: z GEMM (K=1024) + gates
        {
            ull acc0 = 0ull, acc1 = 0ull;
            const int base = (j << 2);
            for (int kb = 0; kb < 1024; kb += 64) {
#pragma unroll
                for (int u = 0; u < 4; u++) {
                    int e = tid + 256*u;
                    int mm = e & 63, kq = e >> 6;
                    int kk = kb + kq*4;
                    float4 v = (kk < 512)
                        ? *(const float4*)(g_aprev + (size_t)mm*HH + kk)
                        : *(const float4*)(&g_h[cur][(size_t)mm*HH + kk - 512]);
                    As[kq*4+0][mm] = v.x; As[kq*4+1][mm] = v.y;
                    As[kq*4+2][mm] = v.z; As[kq*4+3][mm] = v.w;
                }
#pragma unroll
                for (int u = 0; u < 2; u++) {
                    int e = tid + 256*u;
                    int pr = e >> 6, k = e & 63;
                    int gp = pr >> 2, hq2 = pr & 3;
                    const float* w0 = g_W2T + (size_t)((gp*2)*HH + base + hq2)*1024 + kb + k;
                    float f0 = w0[0];
                    float f1 = w0[(size_t)HH*1024];
                    Bs2[pr][k] = pack2(f0, f1);
                }
                __syncthreads();
#pragma unroll 8
                for (int k = 0; k < 64; k++) {
                    float a = As[k][m];
                    ull a2 = pack2(a, a);
                    acc0 = fma2(a2, Bs2[hq][k],     acc0);
                    acc1 = fma2(a2, Bs2[4 + hq][k], acc1);
                }
                __syncthreads();
            }
            int h = base + hq;
            float2 v0 = unpack2(acc0);
            float2 v1 = unpack2(acc1);
            size_t zr = (size_t)(t*BB + m)*Z4H;
            float zi = v0.x + g_zx[zr + h];
            float zf = v0.y + g_zx[zr + 512 + h];
            float zg = v1.x + g_zx[zr + 1024 + h];
            float zo = v1.y + g_zx[zr + 1536 + h];
            float ii = 1.f/(1.f + expf(-zi));
            float ff = 1.f/(1.f + expf(-zf));
            float oo = 1.f/(1.f + expf(-zo));
            float c2 = ff*g_c[m*HH + h] + ii*tanhf(zg);
            float h2 = oo*tanhf(c2);
            g_c[m*HH + h] = c2;
            g_h[nxt][m*HH + h] = h2;
        }
        gbar();

        // phase B: q = h2 @ WqT
        {
            const int n0 = j << 2;
            float acc = 0.f;
            for (int kb = 0; kb < HH; kb += 64) {
#pragma unroll
                for (int u = 0; u < 4; u++) {
                    int e = tid + 256*u;
                    int mm = e & 63, kq = e >> 6;
                    float4 v = *(const float4*)(&g_h[nxt][(size_t)mm*HH + kb + kq*4]);
                    As[kq*4+0][mm] = v.x; As[kq*4+1][mm] = v.y;
                    As[kq*4+2][mm] = v.z; As[kq*4+3][mm] = v.w;
                }
                if (tid < 64) {
                    int n = tid >> 4, k4 = (tid & 15)*4;
                    *(float4*)&Bq[n][k4] = *(const float4*)(g_WqT + (size_t)(n0 + n)*HH + kb + k4);
                }
                __syncthreads();
#pragma unroll 16
                for (int k = 0; k < 64; k++) acc += As[k][m] * Bq[nq][k];
                __syncthreads();
            }
            g_q[m*HH + n0 + nq] = acc;
        }
        gbar();

        // phase C: scores
        {
            int b = j >> 1, sh = (j & 1) * 16;
            for (int i = tid; i < HH; i += 256) { qs[i] = g_q[b*HH + i]; vs[i] = vvec[i]; }
            __syncthreads();
            int w = tid >> 5, lane = tid & 31;
#pragma unroll
            for (int si = 0; si < 2; si++) {
                int s = sh + (w << 1) + si;
                const float* kp = g_keys + (size_t)(b*SS + s)*HH;
                float acc = 0.f;
                for (int h = lane; h < HH; h += 32)
                    acc += tanh_a(kp[h] + qs[h]) * vs[h];
#pragma unroll
                for (int off = 16; off; off >>= 1)
                    acc += __shfl_down_sync(0xffffffffu, acc, off);
                if (lane == 0) g_score[b*SS + s] = acc;
            }
            __syncthreads();
        }
        gbar();

        // phase D: softmax + ctx part
        if (j < BB) {
            int b = j;
            if (tid < SS) sc2[tid] = g_score[b*SS + tid];
            __syncthreads();
            if (tid < SS) {
                float x = sc2[tid];
                float mx = x;
#pragma unroll
                for (int off = 16; off; off >>= 1) mx = fmaxf(mx, __shfl_xor_sync(0xffffffffu, mx, off));
                float e = expf(x - mx);
                float sm = e;
#pragma unroll
                for (int off = 16; off; off >>= 1) sm += __shfl_xor_sync(0xffffffffu, sm, off);
                al2[tid] = e / sm;
            }
            __syncthreads();
            for (int n = tid; n < HH; n += 256) {
                float acc = 0.f;
#pragma unroll
                for (int s = 0; s < SS; s++)
                    acc += al2[s] * g_P[(size_t)(b*SS + s)*HH + n];
                g_ctxa[b*HH + n] = acc;
            }
        }
        gbar();

        // phase E: attn2 = h2@WaT + ctxa
        {
            const int n0 = j << 2;
            float acc = 0.f;
            for (int kb = 0; kb < HH; kb += 64) {
#pragma unroll
                for (int u = 0; u < 4; u++) {
                    int e = tid + 256*u;
                    int mm = e & 63, kq = e >> 6;
                    float4 v = *(const float4*)(&g_h[nxt][(size_t)mm*HH + kb + kq*4]);
                    As[kq*4+0][mm] = v.x; As[kq*4+1][mm] = v.y;
                    As[kq*4+2][mm] = v.z; As[kq*4+3][mm] = v.w;
                }
                if (tid < 64) {
                    int n = tid >> 4, k4 = (tid & 15)*4;
                    *(float4*)&Bq[n][k4] = *(const float4*)(g_WaT + (size_t)(n0 + n)*HH + kb + k4);
                }
                __syncthreads();
#pragma unroll 16
                for (int k = 0; k < 64; k++) acc += As[k][m] * Bq[nq][k];
                __syncthreads();
            }
            int nc = n0 + nq;
            float val = acc + g_ctxa[m*HH + nc];
            g_aprev[m*HH + nc] = val;
            g_attn2all[((size_t)m*TT + t)*HH + nc] = val;
        }
        if (t < TT - 1) gbar();
    }
}

// ------------- bf16 hi/lo conversion: A = attn2all [1984x512] -> [2048x512] ---
__global__ void k_cvtA() {
    int idx = blockIdx.x * blockDim.x + threadIdx.x;
    if (idx >= MPAD*HH) return;
    int row = idx >> 9;
    float v = (row < BB*TT) ? g_attn2all[idx] : 0.f;
    __nv_bfloat16 h = __float2bfloat16(v);
    g_Ah[idx] = h;
    g_Al[idx] = __float2bfloat16(v - __bfloat162float(h));
}

// ------------- bf16 hi/lo transpose: Wfc [512][34004] -> B [34048][512] -------
__global__ void k_cvtB(const float* __restrict__ Wfc) {
    __shared__ float ts[32][33];
    int n0 = blockIdx.x * 32;
    int k0 = blockIdx.y * 32;
    int tx = threadIdx.x, ty = threadIdx.y;   // (32, 8)
#pragma unroll
    for (int i = 0; i < 4; i++) {
        int kk = ty + 8*i;
        int n = n0 + tx;
        ts[kk][tx] = (n < VV) ? Wfc[(size_t)(k0 + kk)*VV + n] : 0.f;
    }
    __syncthreads();
#pragma unroll
    for (int i = 0; i < 4; i++) {
        int nl = ty + 8*i;
        float v = ts[tx][nl];
        __nv_bfloat16 h = __float2bfloat16(v);
        size_t o = (size_t)(n0 + nl)*HH + k0 + tx;
        g_Bh[o] = h;
        g_Bl[o] = __float2bfloat16(v - __bfloat162float(h));
    }
}

// ------------- logits via mma.sync bf16 3-term split --------------------------
// C[2048x34048] = Ah@BhT + Ah@BlT + Al@BhT   (K=512), + bias
// smem stage: Ah/Al/Bh/Bl tiles 128 rows x 32 k (rows padded to 80B)
#define ROWB 80
#define TILEB (128*ROWB)        // 10240
#define STAGEB (4*TILEB)        // 40960
#define SMEM_MMA (2*STAGEB)     // 81920

__device__ __forceinline__ void ldsm4(uint32_t* r, uint32_t addr) {
    asm volatile("ldmatrix.sync.aligned.m8n8.x4.shared.b16 {%0,%1,%2,%3}, [%4];"
                 : "=r"(r[0]), "=r"(r[1]), "=r"(r[2]), "=r"(r[3]) : "r"(addr));
}
__device__ __forceinline__ void ldsm2(uint32_t* r, uint32_t addr) {
    asm volatile("ldmatrix.sync.aligned.m8n8.x2.shared.b16 {%0,%1}, [%2];"
                 : "=r"(r[0]), "=r"(r[1]) : "r"(addr));
}
__device__ __forceinline__ void mma16816(float* c, const uint32_t* a, const uint32_t* b) {
    asm volatile("mma.sync.aligned.m16n8k16.row.col.f32.bf16.bf16.f32 "
                 "{%0,%1,%2,%3}, {%4,%5,%6,%7}, {%8,%9}, {%0,%1,%2,%3};"
                 : "+f"(c[0]), "+f"(c[1]), "+f"(c[2]), "+f"(c[3])
                 : "r"(a[0]), "r"(a[1]), "r"(a[2]), "r"(a[3]), "r"(b[0]), "r"(b[1]));
}
__device__ __forceinline__ void cpasync16(uint32_t saddr, const void* g) {
    asm volatile("cp.async.cg.shared.global [%0], [%1], 16;" :: "r"(saddr), "l"(g));
}

__global__ void __launch_bounds__(256, 1) k_logits_mma(const float* __restrict__ bias,
                                                       float* __restrict__ C) {
    extern __shared__ char smem[];
    const uint32_t sb = smem_u32(smem);
    const int tid = threadIdx.x;
    const int wid = tid >> 5, lane = tid & 31;
    const int warpM = wid >> 2, warpN = wid & 3;    // 2 x 4
    const int bm = blockIdx.y * 128;
    const int bn = blockIdx.x * 128;

    float acc[4][4][4];
#pragma unroll
    for (int i = 0; i < 4; i++)
#pragma unroll
        for (int jj = 0; jj < 4; jj++)
#pragma unroll
            for (int q = 0; q < 4; q++) acc[i][jj][q] = 0.f;

    // stage loader: 4 buffers x 512 16B-chunks; 256 threads x 2 chunks per buffer
    auto load_stage = [&](int st, int kt) {
        uint32_t base = sb + st * STAGEB;
        const int k0 = kt * 32;
#pragma unroll
        for (int i = 0; i < 2; i++) {
            int c = tid + 256*i;
            int row = c >> 2, ch = c & 3;
            uint32_t so = (uint32_t)(row*ROWB + ch*16);
            size_t gA = (size_t)(bm + row)*HH + k0 + ch*8;
            size_t gB = (size_t)(bn + row)*HH + k0 + ch*8;
            cpasync16(base + 0*TILEB + so, g_Ah + gA);
            cpasync16(base + 1*TILEB + so, g_Al + gA);
            cpasync16(base + 2*TILEB + so, g_Bh + gB);
            cpasync16(base + 3*TILEB + so, g_Bl + gB);
        }
        asm volatile("cp.async.commit_group;");
    };

    load_stage(0, 0);

    // ldmatrix lane addressing
    const int jA = lane >> 3;
    const int rowA = (jA & 1)*8 + (lane & 7);        // within 16-row tile
    const int colA = (jA >> 1)*16;                   // byte offset within k16 span
    const int rowB = lane & 7;
    const int colB = ((lane >> 3) & 1)*16;

    for (int kt = 0; kt < 16; kt++) {
        if (kt < 15) load_stage((kt + 1) & 1, kt + 1);
        if (kt < 15) asm volatile("cp.async.wait_group 1;");
        else         asm volatile("cp.async.wait_group 0;");
        __syncthreads();

        uint32_t base = sb + (kt & 1) * STAGEB;
        uint32_t sAh = base, sAl = base + TILEB, sBh = base + 2*TILEB, sBl = base + 3*TILEB;

#pragma unroll
        for (int ks = 0; ks < 2; ks++) {
            uint32_t ah[4][4], al[4][4], bh[4][2], bl[4][2];
#pragma unroll
            for (int mt = 0; mt < 4; mt++) {
                uint32_t off = (uint32_t)((warpM*64 + mt*16 + rowA)*ROWB + ks*32 + colA);
                ldsm4(ah[mt], sAh + off);
                ldsm4(al[mt], sAl + off);
            }
#pragma unroll
            for (int nt = 0; nt < 4; nt++) {
                uint32_t off = (uint32_t)((warpN*32 + nt*8 + rowB)*ROWB + ks*32 + colB);
                ldsm2(bh[nt], sBh + off);
                ldsm2(bl[nt], sBl + off);
            }
#pragma unroll
            for (int mt = 0; mt < 4; mt++)
#pragma unroll
                for (int nt = 0; nt < 4; nt++) {
                    mma16816(acc[mt][nt], ah[mt], bh[nt]);
                    mma16816(acc[mt][nt], ah[mt], bl[nt]);
                    mma16816(acc[mt][nt], al[mt], bh[nt]);
                }
        }
        __syncthreads();
    }

    // epilogue
    const int g = lane >> 2, tg = lane & 3;
#pragma unroll
    for (int mt = 0; mt < 4; mt++) {
        int row0 = bm + warpM*64 + mt*16 + g;
        int row1 = row0 + 8;
#pragma unroll
        for (int nt = 0; nt < 4; nt++) {
            int col = bn + warpN*32 + nt*8 + tg*2;
            if (col >= VV) continue;
            float2 bi = *(const float2*)(bias + col);
            if (row0 < BB*TT) {
                float2 o; o.x = acc[mt][nt][0] + bi.x; o.y = acc[mt][nt][1] + bi.y;
                *(float2*)(C + (size_t)row0*VV + col) = o;
            }
            if (row1 < BB*TT) {
                float2 o; o.x = acc[mt][nt][2] + bi.x; o.y = acc[mt][nt][3] + bi.y;
                *(float2*)(C + (size_t)row1*VV + col) = o;
            }
        }
    }
}

// ----------------------------- launch sequence --------------------------------
extern "C" void kernel_launch(void* const* d_in, const int* in_sizes, int n_in,
                              void* d_out, int out_size) {
    const void*  dec    = d_in[0];
    const float* memory = (const float*)d_in[1];
    const float* h0     = (const float*)d_in[2];
    const float* c0     = (const float*)d_in[3];
    const float* emb    = (const float*)d_in[4];
    const float* Wk     = (const float*)d_in[5];
    const float* Wr     = (const float*)d_in[6];
    const float* bb     = (const float*)d_in[7];
    const float* Wm     = (const float*)d_in[8];
    const float* Wq     = (const float*)d_in[9];
    const float* vv     = (const float*)d_in[10];
    const float* Wa     = (const float*)d_in[11];
    const float* Wfc    = (const float*)d_in[12];
    const float* bfc    = (const float*)d_in[13];
    float* out = (float*)d_out;

    cudaFuncSetAttribute(k_logits_mma, cudaFuncAttributeMaxDynamicSharedMemorySize, SMEM_MMA);

    k_init<<<(BB*TT*EE + 255)/256, 256>>>(dec, h0, c0, emb);
    k_tw<<<(Z4H*1024 + 2*HH*HH + 255)/256, 256>>>(Wk, Wr, Wq, Wa);
    k_zx<<<dim3(Z4H/64, TT), 256>>>(Wk, bb);
    k_kp<<<dim3(HH/64, (BB*SS)/64), 256>>>(memory, Wm, 0);
    k_kp<<<dim3(HH/64, (BB*SS)/64), 256>>>(memory, Wa + HH*HH, 1);
    k_cvtB<<<dim3(NPAD/32, HH/32), dim3(32, 8)>>>(Wfc);
    k_loop<<<NBLK, 256>>>(vv);
    k_cvtA<<<(MPAD*HH + 255)/256, 256>>>();
    k_logits_mma<<<dim3(NPAD/128, MPAD/128), 256, SMEM_MMA>>>(bfc, out);
}

// round 7
// speedup vs baseline: 2.3804x; 1.0389x over previous
#include <cuda_runtime.h>
#include <cuda_bf16.h>
#include <cstdint>
#include <cstddef>

#define BB 64
#define TT 31
#define SS 32
#define VV 34004
#define EE 300
#define HH 512
#define MD 1024
#define BH (BB*HH)
#define Z4H 2048
#define NBLK 128
#define NPAD 34048            // 266 * 128
#define MPAD 2048
#define NXB 266
#define MMAB (16*NXB)         // 4256
#define GRID_FUSED (NBLK + MMAB)

typedef unsigned long long ull;

// ----------------------------- device scratch --------------------------------
__device__ __align__(16) float g_keys[BB*SS*HH];
__device__ __align__(16) float g_P[BB*SS*HH];
__device__ __align__(16) float g_x[BB*TT*EE];
__device__ __align__(16) float g_zx[BB*TT*Z4H];
__device__ __align__(16) float g_W2T[Z4H*1024];
__device__ __align__(16) float g_WqT[HH*HH];
__device__ __align__(16) float g_WaT[HH*HH];
__device__ __align__(16) float g_h[2][BH];
__device__ __align__(16) float g_c[BH];
__device__ __align__(16) float g_aprev[BH];
__device__ __align__(16) float g_q[BH];
__device__ __align__(16) float g_e[BH];
__device__ __align__(16) float g_score[BB*SS];
__device__ __align__(16) __nv_bfloat16 g_Ah[MPAD*HH];          // rows t*64+b
__device__ __align__(16) __nv_bfloat16 g_Al[MPAD*HH];
__device__ __align__(16) __nv_bfloat16 g_Bh[(size_t)NPAD*HH];
__device__ __align__(16) __nv_bfloat16 g_Bl[(size_t)NPAD*HH];
__device__ unsigned g_cnt;
__device__ unsigned g_gen;

// ----------------------------- scalar helpers --------------------------------
__device__ __forceinline__ ull pack2(float x, float y) {
    ull r; asm("mov.b64 %0, {%1,%2};" : "=l"(r) : "f"(x), "f"(y)); return r;
}
__device__ __forceinline__ ull fma2(ull a, ull b, ull c) {
    ull d; asm("fma.rn.f32x2 %0, %1, %2, %3;" : "=l"(d) : "l"(a), "l"(b), "l"(c)); return d;
}
__device__ __forceinline__ float2 unpack2(ull a) {
    float2 f; asm("mov.b64 {%0,%1}, %2;" : "=f"(f.x), "=f"(f.y) : "l"(a)); return f;
}
__device__ __forceinline__ float tanh_a(float x) {
    float y; asm("tanh.approx.f32 %0, %1;" : "=f"(y) : "f"(x)); return y;
}
__device__ __forceinline__ uint32_t smem_u32(const void* p) {
    uint32_t a;
    asm("{ .reg .u64 t; cvta.to.shared.u64 t, %1; cvt.u32.u64 %0, t; }" : "=r"(a) : "l"(p));
    return a;
}
__device__ __forceinline__ unsigned ldg_cg_u32(const unsigned* p) {
    unsigned v; asm volatile("ld.global.cg.u32 %0, [%1];" : "=r"(v) : "l"(p)); return v;
}

__device__ __forceinline__ void gbar() {
    __syncthreads();
    if (threadIdx.x == 0) {
        __threadfence();
        unsigned g = ((volatile unsigned*)&g_gen)[0];
        if (atomicAdd(&g_cnt, 1u) == NBLK - 1) {
            g_cnt = 0;
            __threadfence();
            atomicExch(&g_gen, g + 1);
        } else {
            while (((volatile unsigned*)&g_gen)[0] == g) { }
            __threadfence();
        }
    }
    __syncthreads();
}

// ----------------------------- init -------------------------------------------
__global__ void k_init(const void* __restrict__ dec,
                       const float* __restrict__ h0,
                       const float* __restrict__ c0,
                       const float* __restrict__ emb) {
    int idx = blockIdx.x * blockDim.x + threadIdx.x;
    const long long* p64 = (const long long*)dec;
    bool is64 = true;
#pragma unroll
    for (int i = 0; i < 4; i++) { long long v = p64[i]; if (v < 0 || v >= VV) is64 = false; }
    if (idx < BB*TT*EE) {
        int i = idx / EE, e = idx - i*EE;       // i = b*TT + t
        int b = i / TT, t = i - b*TT;
        long long tok = is64 ? p64[i] : (long long)((const int*)dec)[i];
        g_x[((size_t)(t*BB + b))*EE + e] = emb[(size_t)tok * EE + e];
    }
    if (idx < BH) { g_h[0][idx] = h0[idx]; g_c[idx] = c0[idx]; g_aprev[idx] = 0.f; }
    if (idx < (MPAD - BB*TT)*HH) {      // zero pad rows 1984..2047
        size_t o = (size_t)(BB*TT)*HH + idx;
        g_Ah[o] = __float2bfloat16(0.f);
        g_Al[o] = __float2bfloat16(0.f);
    }
    if (idx == 0) { g_cnt = 0; g_gen = 0; }
}

// ----------------------------- weight transposes ------------------------------
__global__ void k_tw(const float* __restrict__ Wk, const float* __restrict__ Wr,
                     const float* __restrict__ Wq, const float* __restrict__ Wa) {
    int idx = blockIdx.x * blockDim.x + threadIdx.x;
    const int T1 = Z4H * 1024;
    if (idx < T1) {
        int n = idx >> 10, k = idx & 1023;
        g_W2T[idx] = (k < HH) ? Wk[(size_t)(300 + k)*Z4H + n] : Wr[(size_t)(k - HH)*Z4H + n];
    } else {
        int r = idx - T1;
        if (r < HH*HH) { int n = r >> 9, k = r & 511; g_WqT[r] = Wq[(size_t)k*HH + n]; }
        else {
            r -= HH*HH;
            if (r < HH*HH) { int n = r >> 9, k = r & 511; g_WaT[r] = Wa[(size_t)k*HH + n]; }
        }
    }
}

// --------------- generic GEMM out[2048][512] = A[2048][1024] @ B[1024][512] ---
__global__ void __launch_bounds__(256) k_kp(const float* __restrict__ A,
                                            const float* __restrict__ Bm,
                                            int sel) {
    __shared__ float As[16][65];
    __shared__ float Bsh[16][64];
    float* outp = sel ? g_P : g_keys;
    int bm = blockIdx.y * 64, bn = blockIdx.x * 64;
    int tid = threadIdx.x;
    int tm = (tid >> 4) * 4, tn = (tid & 15) * 4;
    ull acc[4][2];
#pragma unroll
    for (int i = 0; i < 4; i++) { acc[i][0] = 0ull; acc[i][1] = 0ull; }
    for (int kb = 0; kb < MD; kb += 16) {
        int m = tid >> 2, ks = (tid & 3) * 4;
        float4 a4 = *(const float4*)(A + (size_t)(bm + m)*MD + kb + ks);
        As[ks+0][m] = a4.x; As[ks+1][m] = a4.y; As[ks+2][m] = a4.z; As[ks+3][m] = a4.w;
        int kl = tid >> 4, c = (tid & 15) * 4;
        *(float4*)&Bsh[kl][c] = *(const float4*)(Bm + (size_t)(kb + kl)*HH + bn + c);
        __syncthreads();
#pragma unroll
        for (int k = 0; k < 16; k++) {
            float4 bq = *(const float4*)&Bsh[k][tn];
            ull bp0 = pack2(bq.x, bq.y), bp1 = pack2(bq.z, bq.w);
#pragma unroll
            for (int i = 0; i < 4; i++) {
                float a = As[k][tm + i];
                ull p = pack2(a, a);
                acc[i][0] = fma2(p, bp0, acc[i][0]);
                acc[i][1] = fma2(p, bp1, acc[i][1]);
            }
        }
        __syncthreads();
    }
#pragma unroll
    for (int i = 0; i < 4; i++) {
        float2 v0 = unpack2(acc[i][0]), v1 = unpack2(acc[i][1]);
        float4 o; o.x = v0.x; o.y = v0.y; o.z = v1.x; o.w = v1.y;
        *(float4*)(outp + (size_t)(bm + tm + i)*HH + bn + tn) = o;
    }
}

// --------------- zx = x @ Wk[0:300] + bias : [1984][2048] ---------------------
__global__ void __launch_bounds__(256) k_zx(const float* __restrict__ Wk,
                                            const float* __restrict__ bb) {
    __shared__ float As[16][65];
    __shared__ float Bsh[16][64];
    int bm = blockIdx.y * 64, bn = blockIdx.x * 64;
    int tid = threadIdx.x;
    int tm = (tid >> 4) * 4, tn = (tid & 15) * 4;
    ull acc[4][2];
#pragma unroll
    for (int i = 0; i < 4; i++) { acc[i][0] = 0ull; acc[i][1] = 0ull; }
    for (int kb = 0; kb < EE; kb += 16) {
        int m = tid >> 2, ks = (tid & 3) * 4;
        float4 a4 = make_float4(0.f, 0.f, 0.f, 0.f);
        if (kb + ks < EE) a4 = *(const float4*)(g_x + (size_t)(bm + m)*EE + kb + ks);
        As[ks+0][m] = a4.x; As[ks+1][m] = a4.y; As[ks+2][m] = a4.z; As[ks+3][m] = a4.w;
        int kl = tid >> 4, c = (tid & 15) * 4;
        float4 b4 = make_float4(0.f, 0.f, 0.f, 0.f);
        if (kb + kl < EE) b4 = *(const float4*)(Wk + (size_t)(kb + kl)*Z4H + bn + c);
        *(float4*)&Bsh[kl][c] = b4;
        __syncthreads();
#pragma unroll
        for (int k = 0; k < 16; k++) {
            float4 bq = *(const float4*)&Bsh[k][tn];
            ull bp0 = pack2(bq.x, bq.y), bp1 = pack2(bq.z, bq.w);
#pragma unroll
            for (int i = 0; i < 4; i++) {
                float a = As[k][tm + i];
                ull p = pack2(a, a);
                acc[i][0] = fma2(p, bp0, acc[i][0]);
                acc[i][1] = fma2(p, bp1, acc[i][1]);
            }
        }
        __syncthreads();
    }
#pragma unroll
    for (int i = 0; i < 4; i++) {
        float2 v0 = unpack2(acc[i][0]), v1 = unpack2(acc[i][1]);
        float4 o;
        o.x = v0.x + bb[bn + tn + 0]; o.y = v0.y + bb[bn + tn + 1];
        o.z = v1.x + bb[bn + tn + 2]; o.w = v1.y + bb[bn + tn + 3];
        *(float4*)(g_zx + (size_t)(bm + tm + i)*Z4H + bn + tn) = o;
    }
}

// ------------- bf16 hi/lo transpose: Wfc [512][34004] -> B [34048][512] -------
__global__ void k_cvtB(const float* __restrict__ Wfc) {
    __shared__ float ts[32][33];
    int n0 = blockIdx.x * 32;
    int k0 = blockIdx.y * 32;
    int tx = threadIdx.x, ty = threadIdx.y;   // (32, 8)
#pragma unroll
    for (int i = 0; i < 4; i++) {
        int kk = ty + 8*i;
        int n = n0 + tx;
        ts[kk][tx] = (n < VV) ? Wfc[(size_t)(k0 + kk)*VV + n] : 0.f;
    }
    __syncthreads();
#pragma unroll
    for (int i = 0; i < 4; i++) {
        int nl = ty + 8*i;
        float v = ts[tx][nl];
        __nv_bfloat16 h = __float2bfloat16(v);
        size_t o = (size_t)(n0 + nl)*HH + k0 + tx;
        g_Bh[o] = h;
        g_Bl[o] = __float2bfloat16(v - __bfloat162float(h));
    }
}

// ----------------------------- mma primitives ---------------------------------
#define ROWB 80
#define TILEB (128*ROWB)
#define STAGEB (4*TILEB)
#define SMEM_FUSED (2*STAGEB)   // 81920

__device__ __forceinline__ void ldsm4(uint32_t* r, uint32_t addr) {
    asm volatile("ldmatrix.sync.aligned.m8n8.x4.shared.b16 {%0,%1,%2,%3}, [%4];"
                 : "=r"(r[0]), "=r"(r[1]), "=r"(r[2]), "=r"(r[3]) : "r"(addr));
}
__device__ __forceinline__ void ldsm2(uint32_t* r, uint32_t addr) {
    asm volatile("ldmatrix.sync.aligned.m8n8.x2.shared.b16 {%0,%1}, [%2];"
                 : "=r"(r[0]), "=r"(r[1]) : "r"(addr));
}
__device__ __forceinline__ void mma16816(float* c, const uint32_t* a, const uint32_t* b) {
    asm volatile("mma.sync.aligned.m16n8k16.row.col.f32.bf16.bf16.f32 "
                 "{%0,%1,%2,%3}, {%4,%5,%6,%7}, {%8,%9}, {%0,%1,%2,%3};"
                 : "+f"(c[0]), "+f"(c[1]), "+f"(c[2]), "+f"(c[3])
                 : "r"(a[0]), "r"(a[1]), "r"(a[2]), "r"(a[3]), "r"(b[0]), "r"(b[1]));
}
__device__ __forceinline__ void cpasync16(uint32_t saddr, const void* g) {
    asm volatile("cp.async.cg.shared.global [%0], [%1], 16;" :: "r"(saddr), "l"(g));
}

// ----------------------------- loop path ---------------------------------------
__device__ void loop_path(char* smem, const float* __restrict__ vvec) {
    float (*As)[65] = (float(*)[65])(smem);                       // 16640
    ull   (*Bs2)[64] = (ull(*)[64])(smem + 16640);                // 4096
    float* Bq  = (float*)(smem + 16640 + 4096);                   // 1024
    float* Bq2 = Bq + 256;                                        // 1024
    float* qs  = Bq2 + 256;                                       // 2048
    float* vs  = qs + HH;                                         // 2048
    float* sc2 = vs + HH;                                         // 128
    float* al2 = sc2 + SS;                                        // 128

    const int j = blockIdx.x;
    const int tid = threadIdx.x;
    const int m  = tid & 63;
    const int hq = tid >> 6;
    const int nq = tid >> 6;

    for (int t = 0; t < TT; t++) {
        const int cur = t & 1, nxt = cur ^ 1;

        // phase A: z GEMM (K=1024) + gates
        {
            ull acc0 = 0ull, acc1 = 0ull;
            const int base = (j << 2);
            for (int kb = 0; kb < 1024; kb += 64) {
#pragma unroll
                for (int u = 0; u < 4; u++) {
                    int e = tid + 256*u;
                    int mm = e & 63, kq = e >> 6;
                    int kk = kb + kq*4;
                    float4 v = (kk < 512)
                        ? *(const float4*)(g_aprev + (size_t)mm*HH + kk)
                        : *(const float4*)(&g_h[cur][(size_t)mm*HH + kk - 512]);
                    As[kq*4+0][mm] = v.x; As[kq*4+1][mm] = v.y;
                    As[kq*4+2][mm] = v.z; As[kq*4+3][mm] = v.w;
                }
#pragma unroll
                for (int u = 0; u < 2; u++) {
                    int e = tid + 256*u;
                    int pr = e >> 6, k = e & 63;
                    int gp = pr >> 2, hq2 = pr & 3;
                    const float* w0 = g_W2T + (size_t)((gp*2)*HH + base + hq2)*1024 + kb + k;
                    float f0 = w0[0];
                    float f1 = w0[(size_t)HH*1024];
                    Bs2[pr][k] = pack2(f0, f1);
                }
                __syncthreads();
#pragma unroll 8
                for (int k = 0; k < 64; k++) {
                    float a = As[k][m];
                    ull a2 = pack2(a, a);
                    acc0 = fma2(a2, Bs2[hq][k],     acc0);
                    acc1 = fma2(a2, Bs2[4 + hq][k], acc1);
                }
                __syncthreads();
            }
            int h = base + hq;
            float2 v0 = unpack2(acc0);
            float2 v1 = unpack2(acc1);
            size_t zr = (size_t)(t*BB + m)*Z4H;
            float zi = v0.x + g_zx[zr + h];
            float zf = v0.y + g_zx[zr + 512 + h];
            float zg = v1.x + g_zx[zr + 1024 + h];
            float zo = v1.y + g_zx[zr + 1536 + h];
            float ii = 1.f/(1.f + expf(-zi));
            float ff = 1.f/(1.f + expf(-zf));
            float oo = 1.f/(1.f + expf(-zo));
            float c2 = ff*g_c[m*HH + h] + ii*tanhf(zg);
            float h2 = oo*tanhf(c2);
            g_c[m*HH + h] = c2;
            g_h[nxt][m*HH + h] = h2;
        }
        gbar();

        // phase BE: q = h2 @ WqT  AND  e = h2 @ WaT  (shared A tile)
        {
            const int n0 = j << 2;
            float accq = 0.f, acce = 0.f;
            for (int kb = 0; kb < HH; kb += 64) {
#pragma unroll
                for (int u = 0; u < 4; u++) {
                    int e = tid + 256*u;
                    int mm = e & 63, kq = e >> 6;
                    float4 v = *(const float4*)(&g_h[nxt][(size_t)mm*HH + kb + kq*4]);
                    As[kq*4+0][mm] = v.x; As[kq*4+1][mm] = v.y;
                    As[kq*4+2][mm] = v.z; As[kq*4+3][mm] = v.w;
                }
                if (tid < 64) {
                    int n = tid >> 4, k4 = (tid & 15)*4;
                    *(float4*)&Bq[n*64 + k4] = *(const float4*)(g_WqT + (size_t)(n0 + n)*HH + kb + k4);
                } else if (tid < 128) {
                    int t2 = tid - 64;
                    int n = t2 >> 4, k4 = (t2 & 15)*4;
                    *(float4*)&Bq2[n*64 + k4] = *(const float4*)(g_WaT + (size_t)(n0 + n)*HH + kb + k4);
                }
                __syncthreads();
#pragma unroll 16
                for (int k = 0; k < 64; k++) {
                    float a = As[k][m];
                    accq += a * Bq[nq*64 + k];
                    acce += a * Bq2[nq*64 + k];
                }
                __syncthreads();
            }
            g_q[m*HH + n0 + nq] = accq;
            g_e[m*HH + n0 + nq] = acce;
        }
        gbar();

        // phase C: scores
        {
            int b = j >> 1, sh = (j & 1) * 16;
            for (int i = tid; i < HH; i += 256) { qs[i] = g_q[b*HH + i]; vs[i] = vvec[i]; }
            __syncthreads();
            int w = tid >> 5, lane = tid & 31;
#pragma unroll
            for (int si = 0; si < 2; si++) {
                int s = sh + (w << 1) + si;
                const float* kp = g_keys + (size_t)(b*SS + s)*HH;
                float acc = 0.f;
                for (int h = lane; h < HH; h += 32)
                    acc += tanh_a(kp[h] + qs[h]) * vs[h];
#pragma unroll
                for (int off = 16; off; off >>= 1)
                    acc += __shfl_down_sync(0xffffffffu, acc, off);
                if (lane == 0) g_score[b*SS + s] = acc;
            }
            __syncthreads();
        }
        gbar();

        // phase D: softmax + ctx + attn2 = e + ctx, write aprev + bf16 split
        if (j < BB) {
            int b = j;
            if (tid < SS) sc2[tid] = g_score[b*SS + tid];
            __syncthreads();
            if (tid < SS) {
                float x = sc2[tid];
                float mx = x;
#pragma unroll
                for (int off = 16; off; off >>= 1) mx = fmaxf(mx, __shfl_xor_sync(0xffffffffu, mx, off));
                float e = expf(x - mx);
                float sm = e;
#pragma unroll
                for (int off = 16; off; off >>= 1) sm += __shfl_xor_sync(0xffffffffu, sm, off);
                al2[tid] = e / sm;
            }
            __syncthreads();
            for (int n = tid; n < HH; n += 256) {
                float acc = 0.f;
#pragma unroll
                for (int s = 0; s < SS; s++)
                    acc += al2[s] * g_P[(size_t)(b*SS + s)*HH + n];
                float val = g_e[b*HH + n] + acc;
                g_aprev[b*HH + n] = val;
                __nv_bfloat16 hbf = __float2bfloat16(val);
                size_t ar = ((size_t)(t*BB + b))*HH + n;
                g_Ah[ar] = hbf;
                g_Al[ar] = __float2bfloat16(val - __bfloat162float(hbf));
            }
        }
        gbar();   // publishes g_gen = 4*(t+1)
    }
}

// ----------------------------- mma consumer path -------------------------------
__device__ void mma_path(char* smem, int lid2,
                         const float* __restrict__ bias, float* __restrict__ C) {
    const uint32_t sb = smem_u32(smem);
    const int tid = threadIdx.x;
    const int wid = tid >> 5, lane = tid & 31;
    const int warpM = wid >> 2, warpN = wid & 3;
    const int by = lid2 / NXB, bx = lid2 - by*NXB;
    const int bm = by * 128;
    const int bn = bx * 128;

    // gate: rows [bm, bm+128) cover t in {2*by, 2*by+1}
    {
        int tmaxv = 2*by + 1; if (tmaxv > TT-1) tmaxv = TT-1;
        unsigned need = 4u * (unsigned)(tmaxv + 1);
        if (tid == 0) {
            while (ldg_cg_u32(&g_gen) < need)
                asm volatile("nanosleep.u32 256;");
        }
        __syncthreads();
        __threadfence();
    }

    float acc[4][4][4];
#pragma unroll
    for (int i = 0; i < 4; i++)
#pragma unroll
        for (int jj = 0; jj < 4; jj++)
#pragma unroll
            for (int q = 0; q < 4; q++) acc[i][jj][q] = 0.f;

    auto load_stage = [&](int st, int kt) {
        uint32_t base = sb + st * STAGEB;
        const int k0 = kt * 32;
#pragma unroll
        for (int i = 0; i < 2; i++) {
            int c = tid + 256*i;
            int row = c >> 2, ch = c & 3;
            uint32_t so = (uint32_t)(row*ROWB + ch*16);
            size_t gA = (size_t)(bm + row)*HH + k0 + ch*8;
            size_t gB = (size_t)(bn + row)*HH + k0 + ch*8;
            cpasync16(base + 0*TILEB + so, g_Ah + gA);
            cpasync16(base + 1*TILEB + so, g_Al + gA);
            cpasync16(base + 2*TILEB + so, g_Bh + gB);
            cpasync16(base + 3*TILEB + so, g_Bl + gB);
        }
        asm volatile("cp.async.commit_group;");
    };

    load_stage(0, 0);

    const int jA = lane >> 3;
    const int rowA = (jA & 1)*8 + (lane & 7);
    const int colA = (jA >> 1)*16;
    const int rowB = lane & 7;
    const int colB = ((lane >> 3) & 1)*16;

    for (int kt = 0; kt < 16; kt++) {
        if (kt < 15) load_stage((kt + 1) & 1, kt + 1);
        if (kt < 15) asm volatile("cp.async.wait_group 1;");
        else         asm volatile("cp.async.wait_group 0;");
        __syncthreads();

        uint32_t base = sb + (kt & 1) * STAGEB;
        uint32_t sAh = base, sAl = base + TILEB, sBh = base + 2*TILEB, sBl = base + 3*TILEB;

#pragma unroll
        for (int ks = 0; ks < 2; ks++) {
            uint32_t bh[4][2], bl[4][2];
#pragma unroll
            for (int nt = 0; nt < 4; nt++) {
                uint32_t off = (uint32_t)((warpN*32 + nt*8 + rowB)*ROWB + ks*32 + colB);
                ldsm2(bh[nt], sBh + off);
                ldsm2(bl[nt], sBl + off);
            }
#pragma unroll
            for (int mt = 0; mt < 4; mt++) {
                uint32_t ah[4], al[4];
                uint32_t off = (uint32_t)((warpM*64 + mt*16 + rowA)*ROWB + ks*32 + colA);
                ldsm4(ah, sAh + off);
                ldsm4(al, sAl + off);
#pragma unroll
                for (int nt = 0; nt < 4; nt++) {
                    mma16816(acc[mt][nt], ah, bh[nt]);
                    mma16816(acc[mt][nt], ah, bl[nt]);
                    mma16816(acc[mt][nt], al, bh[nt]);
                }
            }
        }
        __syncthreads();
    }

    // epilogue: rows are t*64+b -> C row b*31+t
    const int g = lane >> 2, tg = lane & 3;
#pragma unroll
    for (int mt = 0; mt < 4; mt++) {
        int row0 = bm + warpM*64 + mt*16 + g;
        int row1 = row0 + 8;
#pragma unroll
        for (int nt = 0; nt < 4; nt++) {
            int col = bn + warpN*32 + nt*8 + tg*2;
            if (col >= VV) continue;
            float2 bi = *(const float2*)(bias + col);
            if (row0 < BB*TT) {
                int tt = row0 >> 6, b = row0 & 63;
                float2 o; o.x = acc[mt][nt][0] + bi.x; o.y = acc[mt][nt][1] + bi.y;
                *(float2*)(C + ((size_t)(b*TT + tt))*VV + col) = o;
            }
            if (row1 < BB*TT) {
                int tt = row1 >> 6, b = row1 & 63;
                float2 o; o.x = acc[mt][nt][2] + bi.x; o.y = acc[mt][nt][3] + bi.y;
                *(float2*)(C + ((size_t)(b*TT + tt))*VV + col) = o;
            }
        }
    }
}

// ----------------------------- fused kernel ------------------------------------
__global__ void __launch_bounds__(256, 2) k_fused(const float* __restrict__ vvec,
                                                  const float* __restrict__ bias,
                                                  float* __restrict__ C) {
    extern __shared__ char smem[];
    if (blockIdx.x < NBLK) loop_path(smem, vvec);
    else                   mma_path(smem, blockIdx.x - NBLK, bias, C);
}

// ----------------------------- launch sequence --------------------------------
extern "C" void kernel_launch(void* const* d_in, const int* in_sizes, int n_in,
                              void* d_out, int out_size) {
    const void*  dec    = d_in[0];
    const float* memory = (const float*)d_in[1];
    const float* h0     = (const float*)d_in[2];
    const float* c0     = (const float*)d_in[3];
    const float* emb    = (const float*)d_in[4];
    const float* Wk     = (const float*)d_in[5];
    const float* Wr     = (const float*)d_in[6];
    const float* bb     = (const float*)d_in[7];
    const float* Wm     = (const float*)d_in[8];
    const float* Wq     = (const float*)d_in[9];
    const float* vv     = (const float*)d_in[10];
    const float* Wa     = (const float*)d_in[11];
    const float* Wfc    = (const float*)d_in[12];
    const float* bfc    = (const float*)d_in[13];
    float* out = (float*)d_out;

    cudaFuncSetAttribute(k_fused, cudaFuncAttributeMaxDynamicSharedMemorySize, SMEM_FUSED);

    k_init<<<(BB*TT*EE + 255)/256, 256>>>(dec, h0, c0, emb);
    k_tw<<<(Z4H*1024 + 2*HH*HH + 255)/256, 256>>>(Wk, Wr, Wq, Wa);
    k_zx<<<dim3(Z4H/64, TT), 256>>>(Wk, bb);
    k_kp<<<dim3(HH/64, (BB*SS)/64), 256>>>(memory, Wm, 0);
    k_kp<<<dim3(HH/64, (BB*SS)/64), 256>>>(memory, Wa + HH*HH, 1);
    k_cvtB<<<dim3(NPAD/32, HH/32), dim3(32, 8)>>>(Wfc);
    k_fused<<<GRID_FUSED, 256, SMEM_FUSED>>>(vv, bfc, out);
}